// round 7
// baseline (speedup 1.0000x reference)
#include <cuda_runtime.h>
#include <cstdint>

#define N_NODES 4096
#define F_IN    256
#define F_OUT   64
#define HDIM    64
#define MAX_DEG 64
#define ALPHA   0.2f

#define NB      16                 // nodes per LSTM block
#define NCHUNK  (N_NODES / NB)     // 256 chunks
#define GP      260                // gates smem pitch (floats), 16B-aligned rows

typedef unsigned long long ull;

// ------------------------- device scratch (no mallocs allowed) -------------
__device__ float d_Wh [N_NODES * F_OUT];
__device__ float d_Wh2[N_NODES * F_OUT];
__device__ float d_e1 [N_NODES];
__device__ float d_e2 [N_NODES];
__device__ int   d_ord[N_NODES * MAX_DEG];
__device__ int   d_bins[64];
__device__ int   d_binoff[64];
__device__ int   d_sorted[N_NODES];
__device__ int   d_work;

// ------------------------- K1: Wh = h @ W ----------------------------------
__global__ void k_wh(const float* __restrict__ h, const float* __restrict__ W) {
    extern __shared__ float sm[];
    float* Wsm = sm;                       // [256][64]
    float* hsm = sm + F_IN * F_OUT;        // [32][256]
    const int tid = threadIdx.x;
    const int r0  = blockIdx.x * 32;
    for (int i = tid; i < F_IN * F_OUT; i += 256) Wsm[i] = W[i];
    for (int i = tid; i < 32 * F_IN;    i += 256) hsm[i] = h[(size_t)r0 * F_IN + i];
    __syncthreads();
    const int f  = tid & 63;
    const int rq = tid >> 6;
    float acc[8];
#pragma unroll
    for (int j = 0; j < 8; j++) acc[j] = 0.f;
    for (int k = 0; k < F_IN; k++) {
        const float w = Wsm[k * F_OUT + f];
#pragma unroll
        for (int j = 0; j < 8; j++)
            acc[j] = fmaf(w, hsm[(rq * 8 + j) * F_IN + k], acc[j]);
    }
#pragma unroll
    for (int j = 0; j < 8; j++)
        d_Wh[(r0 + rq * 8 + j) * F_OUT + f] = acc[j];
}

// ------------------------- K1b: e1 = Wh@a1, e2 = Wh@a2 ---------------------
__global__ void k_e(const float* __restrict__ a) {
    const int row  = (blockIdx.x * blockDim.x + threadIdx.x) >> 5;
    const int lane = threadIdx.x & 31;
    if (row >= N_NODES) return;
    const float v0 = d_Wh[row * F_OUT + lane];
    const float v1 = d_Wh[row * F_OUT + 32 + lane];
    float s1 = v0 * a[lane]      + v1 * a[lane + 32];
    float s2 = v0 * a[64 + lane] + v1 * a[96 + lane];
#pragma unroll
    for (int o = 16; o; o >>= 1) {
        s1 += __shfl_xor_sync(0xffffffffu, s1, o);
        s2 += __shfl_xor_sync(0xffffffffu, s2, o);
    }
    if (lane == 0) { d_e1[row] = s1; d_e2[row] = s2; }
}

// ------------------------- K2: attention per node --------------------------
__global__ void k_att(const float* __restrict__ adj) {
    __shared__ int   nbr[64];
    __shared__ float satt[64];
    __shared__ int   wcnt[8];
    __shared__ int   scnt;
    __shared__ float smax, ssum;
    __shared__ float spart[4][64];

    const int i    = blockIdx.x;
    const int tid  = threadIdx.x;
    const int warp = tid >> 5;
    const int lane = tid & 31;

    if (tid == 0) scnt = 0;
    __syncthreads();

    for (int base = 0; base < N_NODES; base += 256) {
        const float v = adj[(size_t)i * N_NODES + base + tid];
        const unsigned m = __ballot_sync(0xffffffffu, v > 0.f);
        if (lane == 0) wcnt[warp] = __popc(m);
        __syncthreads();
        int pref = scnt;
        for (int w = 0; w < warp; w++) pref += wcnt[w];
        if (v > 0.f) {
            const int pos = pref + __popc(m & ((1u << lane) - 1u));
            if (pos < 64) nbr[pos] = base + tid;
        }
        __syncthreads();
        if (tid == 0) {
            int t = 0;
            for (int w = 0; w < 8; w++) t += wcnt[w];
            scnt += t;
        }
        __syncthreads();
    }
    const int L = (scnt < 64) ? scnt : 64;

    const float e1i = d_e1[i];
    if (tid < L) {
        float ev = e1i + d_e2[nbr[tid]];
        ev = ev > 0.f ? ev : ALPHA * ev;
        satt[tid] = ev;
    }
    __syncthreads();
    if (tid == 0) {
        float mx = satt[0];
        for (int n = 1; n < L; n++) mx = fmaxf(mx, satt[n]);
        smax = mx;
    }
    __syncthreads();
    if (tid < L) satt[tid] = __expf(satt[tid] - smax);
    __syncthreads();
    if (tid == 0) {
        float s = 0.f;
        for (int n = 0; n < L; n++) s += satt[n];
        ssum = s;
    }
    __syncthreads();
    if (tid < L) satt[tid] = satt[tid] / ssum;
    __syncthreads();

    if (tid < L) {
        const float av = satt[tid];
        const int   jv = nbr[tid];
        int rank = 0;
        for (int k = 0; k < L; k++) {
            const float ak = satt[k];
            rank += (ak > av) || (ak == av && nbr[k] < jv);
        }
        d_ord[i * MAX_DEG + rank] = jv;
    }

    const int f = tid & 63, s = tid >> 6;
    float part = 0.f;
    for (int n = s; n < L; n += 4)
        part = fmaf(satt[n], d_Wh[nbr[n] * F_OUT + f], part);
    spart[s][f] = part;
    __syncthreads();
    if (s == 0)
        d_Wh2[i * F_OUT + f] = spart[0][f] + spart[1][f] + spart[2][f] + spart[3][f];
}

// ------------------------- K3: counting sort by seq_length desc ------------
__global__ void k_sort_init() {
    const int t = threadIdx.x;
    if (t < 64) d_bins[t] = 0;
    if (t == 0) d_work = 0;
}
__global__ void k_hist(const int* __restrict__ sl) {
    const int i = blockIdx.x * blockDim.x + threadIdx.x;
    if (i < N_NODES) atomicAdd(&d_bins[64 - sl[i]], 1);
}
__global__ void k_scan() {
    if (threadIdx.x == 0) {
        int acc = 0;
        for (int b = 0; b < 64; b++) { d_binoff[b] = acc; acc += d_bins[b]; }
    }
}
__global__ void k_scatter(const int* __restrict__ sl) {
    const int i = blockIdx.x * blockDim.x + threadIdx.x;
    if (i < N_NODES) {
        const int p = atomicAdd(&d_binoff[64 - sl[i]], 1);
        d_sorted[p] = i;
    }
}

// ------------------------- K4: persistent LSTM (f32x2 packed) --------------
// SMEM: wih 16384 + whh 16384 + b 256 + x_dup 2048 + h_dup 2048 + c 1024 + g 16*GP
#define LSTM_SMEM_FLOATS (2 * 64 * 256 + 256 + 2 * 64 * 32 + 64 * 16 + NB * GP)
#define LSTM_SMEM_BYTES  (LSTM_SMEM_FLOATS * 4 + 64 * 4)

__device__ __forceinline__ void fma2(ull& d, ull a, ull b) {
    asm("fma.rn.f32x2 %0, %1, %2, %0;" : "+l"(d) : "l"(a), "l"(b));
}

__device__ __forceinline__ float sigf(float x) { return 1.f / (1.f + __expf(-x)); }

__global__ __launch_bounds__(256, 1)
void k_lstm(const float* __restrict__ w_ih, const float* __restrict__ w_hh,
            const float* __restrict__ b_ih, const float* __restrict__ b_hh,
            const int* __restrict__ sl, float* __restrict__ out) {
    extern __shared__ float sm[];
    float* s_wih = sm;                      // [64][256]  k-major (transposed)
    float* s_whh = s_wih + 64 * 256;        // [64][256]
    float* s_b   = s_whh + 64 * 256;        // [256]
    float* x_dup = s_b + 256;               // [64][32]  node m duplicated at 2m,2m+1
    float* h_dup = x_dup + 64 * 32;         // [64][32]
    float* c_sm  = h_dup + 64 * 32;         // [64][16]
    float* g_sm  = c_sm + 64 * 16;          // [16][GP]
    int*   s_node = (int*)(g_sm + NB * GP); // [16]
    int*   s_L    = s_node + NB;            // [16]
    int*   s_meta = s_L + NB;               // [0]=chunk

    const int tid = threadIdx.x;

    // load transposed weights + fused bias
    for (int idx = tid; idx < 256 * 64; idx += 256) {
        const int g = idx >> 6, k = idx & 63;
        s_wih[k * 256 + g] = w_ih[idx];
        s_whh[k * 256 + g] = w_hh[idx];
    }
    s_b[tid] = b_ih[tid] + b_hh[tid];
    __syncthreads();   // R4 fix: cross-warp read of s_b below

    const int q = tid & 63;       // gate quad index (gates 4q..4q+3)
    const int s = tid >> 6;       // node subgroup (4 nodes each)
    const ulonglong2* wih2 = (const ulonglong2*)s_wih;   // row k = 64 ulonglong2
    const ulonglong2* whh2 = (const ulonglong2*)s_whh;
    const ulonglong2* xd2  = (const ulonglong2*)x_dup;   // row k = 8 ulonglong2
    const ulonglong2* hd2  = (const ulonglong2*)h_dup;
    const ull b01 = ((const ull*)s_b)[2 * q];
    const ull b23 = ((const ull*)s_b)[2 * q + 1];

    // gather mapping: thread owns (node gm, float4-chunk gk4)
    const int gm  = tid >> 4;     // 0..15
    const int gk4 = tid & 15;     // 0..15

    while (true) {
        __syncthreads();
        if (tid == 0) s_meta[0] = atomicAdd(&d_work, 1);
        __syncthreads();
        const int chunk = s_meta[0];
        if (chunk >= NCHUNK) break;

        if (tid < NB) {
            const int node = d_sorted[chunk * NB + tid];
            s_node[tid] = node;
            s_L[tid]    = sl[node];
        }
        for (int idx = tid; idx < 64 * 32; idx += 256) h_dup[idx] = 0.f;
        for (int idx = tid; idx < 64 * 16; idx += 256) c_sm[idx] = 0.f;
        __syncthreads();
        if (tid == 0) {
            int mx = 0;
            for (int m = 0; m < NB; m++) mx = max(mx, s_L[m]);
            s_meta[1] = mx;
        }
        __syncthreads();
        const int maxL = s_meta[1];
        const int Lg   = s_L[gm];
        const int obase = s_node[gm] * MAX_DEG;

        // prefetch x for t=0
        float4 xv;
        {
            int idx = Lg - 1; if (idx < 0) idx = 0;
            const int row = d_ord[obase + idx];
            xv = *(const float4*)(&d_Wh2[row * F_OUT + gk4 * 4]);
        }

        for (int t = 0; t < maxL; t++) {
            // write duplicated x for this step
            {
                float* xb = x_dup + (gk4 * 4) * 32 + 2 * gm;
                *(float2*)(xb)          = make_float2(xv.x, xv.x);
                *(float2*)(xb + 32)     = make_float2(xv.y, xv.y);
                *(float2*)(xb + 64)     = make_float2(xv.z, xv.z);
                *(float2*)(xb + 96)     = make_float2(xv.w, xv.w);
            }
            __syncthreads();

            // prefetch next step's x (LDG latency hides under the GEMM)
            if (t + 1 < maxL) {
                int idx = Lg - 2 - t; if (idx < 0) idx = 0;
                const int row = d_ord[obase + idx];
                xv = *(const float4*)(&d_Wh2[row * F_OUT + gk4 * 4]);
            }

            // gate GEMM: 4 nodes x 4 gates per thread, f32x2 over gate pairs
            ull a0p = b01, a0q = b23, a1p = b01, a1q = b23;
            ull a2p = b01, a2q = b23, a3p = b01, a3q = b23;
#pragma unroll 8
            for (int k = 0; k < 64; k++) {
                const ulonglong2 wi = wih2[k * 64 + q];
                const ulonglong2 wh = whh2[k * 64 + q];
                const ulonglong2 xA = xd2[k * 8 + 2 * s];      // nodes 4s,4s+1 (dup)
                const ulonglong2 xB = xd2[k * 8 + 2 * s + 1];  // nodes 4s+2,4s+3
                const ulonglong2 hA = hd2[k * 8 + 2 * s];
                const ulonglong2 hB = hd2[k * 8 + 2 * s + 1];
                fma2(a0p, wi.x, xA.x); fma2(a0q, wi.y, xA.x);
                fma2(a1p, wi.x, xA.y); fma2(a1q, wi.y, xA.y);
                fma2(a2p, wi.x, xB.x); fma2(a2q, wi.y, xB.x);
                fma2(a3p, wi.x, xB.y); fma2(a3q, wi.y, xB.y);
                fma2(a0p, wh.x, hA.x); fma2(a0q, wh.y, hA.x);
                fma2(a1p, wh.x, hA.y); fma2(a1q, wh.y, hA.y);
                fma2(a2p, wh.x, hB.x); fma2(a2q, wh.y, hB.x);
                fma2(a3p, wh.x, hB.y); fma2(a3q, wh.y, hB.y);
            }
            {
                ull* g0 = (ull*)(g_sm + (4 * s + 0) * GP);
                ull* g1 = (ull*)(g_sm + (4 * s + 1) * GP);
                ull* g2 = (ull*)(g_sm + (4 * s + 2) * GP);
                ull* g3 = (ull*)(g_sm + (4 * s + 3) * GP);
                g0[2 * q] = a0p; g0[2 * q + 1] = a0q;
                g1[2 * q] = a1p; g1[2 * q + 1] = a1q;
                g2[2 * q] = a2p; g2[2 * q + 1] = a2q;
                g3[2 * q] = a3p; g3[2 * q + 1] = a3q;
            }
            __syncthreads();

            // gate nonlinearity + state update (only active nodes)
#pragma unroll
            for (int rep = 0; rep < 4; rep++) {
                const int idx = tid + rep * 256;
                const int m = idx & 15, u = idx >> 4;
                if (t < s_L[m]) {
                    const float gi = g_sm[m * GP + u];
                    const float gf = g_sm[m * GP + 64 + u];
                    const float gg = g_sm[m * GP + 128 + u];
                    const float go = g_sm[m * GP + 192 + u];
                    const float c  = c_sm[u * 16 + m];
                    const float cn = sigf(gf) * c + sigf(gi) * tanhf(gg);
                    const float hn = sigf(go) * tanhf(cn);
                    c_sm[u * 16 + m] = cn;
                    *(float2*)(h_dup + u * 32 + 2 * m) = make_float2(hn, hn);
                }
            }
            __syncthreads();
        }

        // write hn
#pragma unroll
        for (int rep = 0; rep < 4; rep++) {
            const int idx = tid + rep * 256;
            const int m = idx & 15, u = idx >> 4;
            out[s_node[m] * HDIM + u] = h_dup[u * 32 + 2 * m];
        }
    }
}

// ------------------------- launch ------------------------------------------
extern "C" void kernel_launch(void* const* d_in, const int* in_sizes, int n_in,
                              void* d_out, int out_size) {
    const float* h   = (const float*)d_in[0];
    const float* adj = (const float*)d_in[1];
    const int*   sl  = (const int*)  d_in[2];
    const float* W   = (const float*)d_in[3];
    const float* a   = (const float*)d_in[4];
    const float* wih = (const float*)d_in[5];
    const float* whh = (const float*)d_in[6];
    const float* bih = (const float*)d_in[7];
    const float* bhh = (const float*)d_in[8];
    float* out = (float*)d_out;

    cudaFuncSetAttribute(k_wh,   cudaFuncAttributeMaxDynamicSharedMemorySize, 96 * 1024);
    cudaFuncSetAttribute(k_lstm, cudaFuncAttributeMaxDynamicSharedMemorySize, LSTM_SMEM_BYTES);

    int sms = 148;
    cudaDeviceGetAttribute(&sms, cudaDevAttrMultiProcessorCount, 0);

    k_wh      <<<128,  256, 96 * 1024>>>(h, W);
    k_e       <<<512,  256>>>(a);
    k_sort_init<<<1,    64>>>();
    k_hist    <<<16,   256>>>(sl);
    k_att     <<<4096, 256>>>(adj);
    k_scan    <<<1,     32>>>();
    k_scatter <<<16,   256>>>(sl);
    k_lstm    <<<sms,  256, LSTM_SMEM_BYTES>>>(wih, whh, bih, bhh, sl, out);
}

// round 8
// speedup vs baseline: 1.1276x; 1.1276x over previous
#include <cuda_runtime.h>
#include <cstdint>

#define N_NODES 4096
#define F_IN    256
#define F_OUT   64
#define HDIM    64
#define MAX_DEG 64
#define ALPHA   0.2f

#define NB      16                 // nodes per LSTM block
#define NCHUNK  (N_NODES / NB)     // 256 chunks
#define GP      260                // gates smem pitch (floats)
#define XP      20                 // x/h smem row pitch (floats, 16B-aligned, anti-conflict)

typedef unsigned long long ull;

// ------------------------- device scratch (no mallocs allowed) -------------
__device__ float d_Wh [N_NODES * F_OUT];
__device__ float d_Wh2[N_NODES * F_OUT];
__device__ float d_e1 [N_NODES];
__device__ float d_e2 [N_NODES];
__device__ int   d_ord[N_NODES * MAX_DEG];
__device__ int   d_bins[64];
__device__ int   d_sorted[N_NODES];
__device__ int   d_work;

// ------------------------- K1: Wh = h @ W ----------------------------------
__global__ void k_wh(const float* __restrict__ h, const float* __restrict__ W) {
    extern __shared__ float sm[];
    float* Wsm = sm;                       // [256][64]
    float* hsm = sm + F_IN * F_OUT;        // [32][256]
    const int tid = threadIdx.x;
    const int r0  = blockIdx.x * 32;
    for (int i = tid; i < F_IN * F_OUT; i += 256) Wsm[i] = W[i];
    for (int i = tid; i < 32 * F_IN;    i += 256) hsm[i] = h[(size_t)r0 * F_IN + i];
    __syncthreads();
    const int f  = tid & 63;
    const int rq = tid >> 6;
    float acc[8];
#pragma unroll
    for (int j = 0; j < 8; j++) acc[j] = 0.f;
    for (int k = 0; k < F_IN; k++) {
        const float w = Wsm[k * F_OUT + f];
#pragma unroll
        for (int j = 0; j < 8; j++)
            acc[j] = fmaf(w, hsm[(rq * 8 + j) * F_IN + k], acc[j]);
    }
#pragma unroll
    for (int j = 0; j < 8; j++)
        d_Wh[(r0 + rq * 8 + j) * F_OUT + f] = acc[j];
}

// ------------------------- K1b: e1 = Wh@a1, e2 = Wh@a2 ---------------------
__global__ void k_e(const float* __restrict__ a) {
    const int row  = (blockIdx.x * blockDim.x + threadIdx.x) >> 5;
    const int lane = threadIdx.x & 31;
    if (row >= N_NODES) return;
    const float v0 = d_Wh[row * F_OUT + lane];
    const float v1 = d_Wh[row * F_OUT + 32 + lane];
    float s1 = v0 * a[lane]      + v1 * a[lane + 32];
    float s2 = v0 * a[64 + lane] + v1 * a[96 + lane];
#pragma unroll
    for (int o = 16; o; o >>= 1) {
        s1 += __shfl_xor_sync(0xffffffffu, s1, o);
        s2 += __shfl_xor_sync(0xffffffffu, s2, o);
    }
    if (lane == 0) { d_e1[row] = s1; d_e2[row] = s2; }
}

// ------------------------- K2: counting sort (2 single-block kernels) ------
__global__ void k_sort_a(const int* __restrict__ sl) {
    __shared__ int hist[64];
    const int t = threadIdx.x;
    if (t < 64) hist[t] = 0;
    __syncthreads();
    for (int i = t; i < N_NODES; i += 1024) atomicAdd(&hist[64 - sl[i]], 1);
    __syncthreads();
    if (t < 64) d_bins[t] = hist[t];
    if (t == 0) d_work = 0;
}
__global__ void k_sort_b(const int* __restrict__ sl) {
    __shared__ int off[64];
    const int t = threadIdx.x;
    if (t == 0) {
        int acc = 0;
        for (int b = 0; b < 64; b++) { off[b] = acc; acc += d_bins[b]; }
    }
    __syncthreads();
    for (int i = t; i < N_NODES; i += 1024) {
        const int p = atomicAdd(&off[64 - sl[i]], 1);
        d_sorted[p] = i;   // order within equal-L bin nondeterministic; per-node
                           // results are chunk-independent, so output is deterministic
    }
}

// ------------------------- K3: attention per node --------------------------
__global__ void k_att(const float* __restrict__ adj) {
    __shared__ int   nbr[64];
    __shared__ float satt[64];
    __shared__ int   wcnt[8];
    __shared__ int   scnt;
    __shared__ float smax, ssum;
    __shared__ float spart[4][64];

    const int i    = blockIdx.x;
    const int tid  = threadIdx.x;
    const int warp = tid >> 5;
    const int lane = tid & 31;

    if (tid == 0) scnt = 0;
    __syncthreads();

    for (int base = 0; base < N_NODES; base += 256) {
        const float v = adj[(size_t)i * N_NODES + base + tid];
        const unsigned m = __ballot_sync(0xffffffffu, v > 0.f);
        if (lane == 0) wcnt[warp] = __popc(m);
        __syncthreads();
        int pref = scnt;
        for (int w = 0; w < warp; w++) pref += wcnt[w];
        if (v > 0.f) {
            const int pos = pref + __popc(m & ((1u << lane) - 1u));
            if (pos < 64) nbr[pos] = base + tid;
        }
        __syncthreads();
        if (tid == 0) {
            int t = 0;
            for (int w = 0; w < 8; w++) t += wcnt[w];
            scnt += t;
        }
        __syncthreads();
    }
    const int L = (scnt < 64) ? scnt : 64;

    const float e1i = d_e1[i];
    if (tid < L) {
        float ev = e1i + d_e2[nbr[tid]];
        ev = ev > 0.f ? ev : ALPHA * ev;
        satt[tid] = ev;
    }
    __syncthreads();
    if (tid == 0) {
        float mx = satt[0];
        for (int n = 1; n < L; n++) mx = fmaxf(mx, satt[n]);
        smax = mx;
    }
    __syncthreads();
    if (tid < L) satt[tid] = __expf(satt[tid] - smax);
    __syncthreads();
    if (tid == 0) {
        float s = 0.f;
        for (int n = 0; n < L; n++) s += satt[n];
        ssum = s;
    }
    __syncthreads();
    if (tid < L) satt[tid] = satt[tid] / ssum;
    __syncthreads();

    if (tid < L) {
        const float av = satt[tid];
        const int   jv = nbr[tid];
        int rank = 0;
        for (int k = 0; k < L; k++) {
            const float ak = satt[k];
            rank += (ak > av) || (ak == av && nbr[k] < jv);
        }
        d_ord[i * MAX_DEG + rank] = jv;
    }

    const int f = tid & 63, s = tid >> 6;
    float part = 0.f;
    for (int n = s; n < L; n += 4)
        part = fmaf(satt[n], d_Wh[nbr[n] * F_OUT + f], part);
    spart[s][f] = part;
    __syncthreads();
    if (s == 0)
        d_Wh2[i * F_OUT + f] = spart[0][f] + spart[1][f] + spart[2][f] + spart[3][f];
}

// ------------------------- K4: persistent LSTM (f32x2 over node pairs) -----
// SMEM floats: wih 16384 + whh 16384 + b 256 + x 64*XP + h 64*XP + c 16*64 + g 16*GP
#define LSTM_SMEM_FLOATS (2 * 64 * 256 + 256 + 2 * 64 * XP + 16 * 64 + NB * GP)
#define LSTM_SMEM_BYTES  (LSTM_SMEM_FLOATS * 4 + 64 * 4)

__device__ __forceinline__ ull pack2(float x) {
    ull r; asm("mov.b64 %0, {%1, %1};" : "=l"(r) : "f"(x)); return r;
}
__device__ __forceinline__ void fma2(ull& d, ull a, ull b) {
    asm("fma.rn.f32x2 %0, %1, %2, %0;" : "+l"(d) : "l"(a), "l"(b));
}
__device__ __forceinline__ float2 unpk(ull v) {
    float2 f; asm("mov.b64 {%0, %1}, %2;" : "=f"(f.x), "=f"(f.y) : "l"(v)); return f;
}
__device__ __forceinline__ float sigf(float x) { return 1.f / (1.f + __expf(-x)); }
__device__ __forceinline__ float tanhfast(float x) {
    const float e = __expf(2.f * x);
    return (e - 1.f) / (e + 1.f);
}

__global__ __launch_bounds__(256, 1)
void k_lstm(const float* __restrict__ w_ih, const float* __restrict__ w_hh,
            const float* __restrict__ b_ih, const float* __restrict__ b_hh,
            const int* __restrict__ sl, float* __restrict__ out) {
    extern __shared__ float sm[];
    float* s_wih = sm;                      // [64][256]  k-major (transposed)
    float* s_whh = s_wih + 64 * 256;        // [64][256]
    float* s_b   = s_whh + 64 * 256;        // [256]
    float* x_sm  = s_b + 256;               // [64][XP]  (16 nodes used)
    float* h_sm  = x_sm + 64 * XP;          // [64][XP]
    float* c_sm  = h_sm + 64 * XP;          // [16][64]
    float* g_sm  = c_sm + 16 * 64;          // [16][GP]  node-major gates
    int*   s_node = (int*)(g_sm + NB * GP); // [16]
    int*   s_L    = s_node + NB;            // [16]
    int*   s_meta = s_L + NB;               // [0]=chunk [1]=maxL

    const int tid = threadIdx.x;

    // load transposed weights + fused bias
    for (int idx = tid; idx < 256 * 64; idx += 256) {
        const int g = idx >> 6, k = idx & 63;
        s_wih[k * 256 + g] = w_ih[idx];
        s_whh[k * 256 + g] = w_hh[idx];
    }
    s_b[tid] = b_ih[tid] + b_hh[tid];
    __syncthreads();   // cross-warp read of s_b below (R4 fix)

    // GEMM mapping: thread owns gates {2*q3, 2*q3+1} for nodes 8*s3 .. 8*s3+7
    const int q3 = tid & 127;
    const int s3 = tid >> 7;
    const float2* wi2 = (const float2*)s_wih;   // [64][128] float2
    const float2* wh2 = (const float2*)s_whh;
    const ull bg0 = pack2(s_b[2 * q3]);
    const ull bg1 = pack2(s_b[2 * q3 + 1]);

    // gather mapping: node gm (low bits -> conflict-free STS), k-chunk gk4
    const int gm  = tid & 15;
    const int gk4 = tid >> 4;

    while (true) {
        __syncthreads();
        if (tid == 0) s_meta[0] = atomicAdd(&d_work, 1);
        __syncthreads();
        const int chunk = s_meta[0];
        if (chunk >= NCHUNK) break;

        if (tid < NB) {
            const int node = d_sorted[chunk * NB + tid];
            s_node[tid] = node;
            s_L[tid]    = sl[node];
        }
        for (int idx = tid; idx < 64 * XP; idx += 256) h_sm[idx] = 0.f;
        for (int idx = tid; idx < 16 * 64; idx += 256) c_sm[idx] = 0.f;
        __syncthreads();
        if (tid == 0) {
            int mx = 0;
            for (int m = 0; m < NB; m++) mx = max(mx, s_L[m]);
            s_meta[1] = mx;
        }
        __syncthreads();
        const int maxL = s_meta[1];
        const int Lg   = s_L[gm];
        const int obase = s_node[gm] * MAX_DEG;

        // prefetch x for t=0
        float4 xv;
        {
            int idx = Lg - 1; if (idx < 0) idx = 0;
            const int row = d_ord[obase + idx];
            xv = *(const float4*)(&d_Wh2[row * F_OUT + gk4 * 4]);
        }

        for (int t = 0; t < maxL; t++) {
            // phase A: write x(t); update state for step t-1
            x_sm[(gk4 * 4 + 0) * XP + gm] = xv.x;
            x_sm[(gk4 * 4 + 1) * XP + gm] = xv.y;
            x_sm[(gk4 * 4 + 2) * XP + gm] = xv.z;
            x_sm[(gk4 * 4 + 3) * XP + gm] = xv.w;
            if (t + 1 < maxL) {     // prefetch next x under this step's work
                int idx = Lg - 2 - t; if (idx < 0) idx = 0;
                const int row = d_ord[obase + idx];
                xv = *(const float4*)(&d_Wh2[row * F_OUT + gk4 * 4]);
            }
            if (t > 0) {
#pragma unroll
                for (int rep = 0; rep < 4; rep++) {
                    const int idx = tid + rep * 256;
                    const int u = idx & 63, m = idx >> 6;
                    if (t - 1 < s_L[m]) {
                        const float gi = g_sm[m * GP + u];
                        const float gf = g_sm[m * GP + 64 + u];
                        const float gg = g_sm[m * GP + 128 + u];
                        const float go = g_sm[m * GP + 192 + u];
                        const float c  = c_sm[m * 64 + u];
                        const float cn = sigf(gf) * c + sigf(gi) * tanhfast(gg);
                        const float hn = sigf(go) * tanhfast(cn);
                        c_sm[m * 64 + u] = cn;
                        h_sm[u * XP + m] = hn;
                    }
                }
            }
            __syncthreads();

            // phase B: gate GEMM, f32x2 packed over adjacent node pairs
            ull a00 = bg0, a01 = bg0, a02 = bg0, a03 = bg0;  // gate 2q3,  node pairs 0..3
            ull a10 = bg1, a11 = bg1, a12 = bg1, a13 = bg1;  // gate 2q3+1
#pragma unroll 4
            for (int k = 0; k < 64; k++) {
                const float2 wi = wi2[k * 128 + q3];
                const float2 wh = wh2[k * 128 + q3];
                const ull wi0 = pack2(wi.x), wi1 = pack2(wi.y);
                const ull wh0 = pack2(wh.x), wh1 = pack2(wh.y);
                const ulonglong2 xa = *(const ulonglong2*)(x_sm + k * XP + 8 * s3);
                const ulonglong2 xb = *(const ulonglong2*)(x_sm + k * XP + 8 * s3 + 4);
                const ulonglong2 ha = *(const ulonglong2*)(h_sm + k * XP + 8 * s3);
                const ulonglong2 hb = *(const ulonglong2*)(h_sm + k * XP + 8 * s3 + 4);
                fma2(a00, wi0, xa.x); fma2(a01, wi0, xa.y);
                fma2(a02, wi0, xb.x); fma2(a03, wi0, xb.y);
                fma2(a10, wi1, xa.x); fma2(a11, wi1, xa.y);
                fma2(a12, wi1, xb.x); fma2(a13, wi1, xb.y);
                fma2(a00, wh0, ha.x); fma2(a01, wh0, ha.y);
                fma2(a02, wh0, hb.x); fma2(a03, wh0, hb.y);
                fma2(a10, wh1, ha.x); fma2(a11, wh1, ha.y);
                fma2(a12, wh1, hb.x); fma2(a13, wh1, hb.y);
            }
            // store gates: per node, adjacent gate pair -> conflict-free STS.64
            {
                const int nb0 = 8 * s3;
                const float2 p00 = unpk(a00), p10 = unpk(a10);
                const float2 p01 = unpk(a01), p11 = unpk(a11);
                const float2 p02 = unpk(a02), p12 = unpk(a12);
                const float2 p03 = unpk(a03), p13 = unpk(a13);
                float* gq = g_sm + 2 * q3;
                *(float2*)(gq + (nb0 + 0) * GP) = make_float2(p00.x, p10.x);
                *(float2*)(gq + (nb0 + 1) * GP) = make_float2(p00.y, p10.y);
                *(float2*)(gq + (nb0 + 2) * GP) = make_float2(p01.x, p11.x);
                *(float2*)(gq + (nb0 + 3) * GP) = make_float2(p01.y, p11.y);
                *(float2*)(gq + (nb0 + 4) * GP) = make_float2(p02.x, p12.x);
                *(float2*)(gq + (nb0 + 5) * GP) = make_float2(p02.y, p12.y);
                *(float2*)(gq + (nb0 + 6) * GP) = make_float2(p03.x, p13.x);
                *(float2*)(gq + (nb0 + 7) * GP) = make_float2(p03.y, p13.y);
            }
            __syncthreads();
        }

        // final update for step maxL-1
#pragma unroll
        for (int rep = 0; rep < 4; rep++) {
            const int idx = tid + rep * 256;
            const int u = idx & 63, m = idx >> 6;
            if (maxL - 1 < s_L[m]) {
                const float gi = g_sm[m * GP + u];
                const float gf = g_sm[m * GP + 64 + u];
                const float gg = g_sm[m * GP + 128 + u];
                const float go = g_sm[m * GP + 192 + u];
                const float c  = c_sm[m * 64 + u];
                const float cn = sigf(gf) * c + sigf(gi) * tanhfast(gg);
                const float hn = sigf(go) * tanhfast(cn);
                c_sm[m * 64 + u] = cn;
                h_sm[u * XP + m] = hn;
            }
        }
        __syncthreads();

        // write hn
#pragma unroll
        for (int rep = 0; rep < 4; rep++) {
            const int idx = tid + rep * 256;
            const int u = idx & 63, m = idx >> 6;
            out[s_node[m] * HDIM + u] = h_sm[u * XP + m];
        }
    }
}

// ------------------------- launch ------------------------------------------
extern "C" void kernel_launch(void* const* d_in, const int* in_sizes, int n_in,
                              void* d_out, int out_size) {
    const float* h   = (const float*)d_in[0];
    const float* adj = (const float*)d_in[1];
    const int*   sl  = (const int*)  d_in[2];
    const float* W   = (const float*)d_in[3];
    const float* a   = (const float*)d_in[4];
    const float* wih = (const float*)d_in[5];
    const float* whh = (const float*)d_in[6];
    const float* bih = (const float*)d_in[7];
    const float* bhh = (const float*)d_in[8];
    float* out = (float*)d_out;

    cudaFuncSetAttribute(k_wh,   cudaFuncAttributeMaxDynamicSharedMemorySize, 96 * 1024);
    cudaFuncSetAttribute(k_lstm, cudaFuncAttributeMaxDynamicSharedMemorySize, LSTM_SMEM_BYTES);

    int sms = 148;
    cudaDeviceGetAttribute(&sms, cudaDevAttrMultiProcessorCount, 0);

    // launch order fixed so ncu (-s 5 -c 1) profiles k_lstm (launch index 5)
    k_wh     <<<128,  256, 96 * 1024>>>(h, W);     // 0
    k_e      <<<512,  256>>>(a);                   // 1
    k_sort_a <<<1,   1024>>>(sl);                  // 2
    k_sort_b <<<1,   1024>>>(sl);                  // 3
    k_att    <<<4096, 256>>>(adj);                 // 4
    k_lstm   <<<sms,  256, LSTM_SMEM_BYTES>>>(wih, whh, bih, bhh, sl, out);  // 5
}

// round 10
// speedup vs baseline: 1.2956x; 1.1489x over previous
#include <cuda_runtime.h>
#include <cstdint>

#define N_NODES 4096
#define F_IN    256
#define F_OUT   64
#define HDIM    64
#define MAX_DEG 64
#define ALPHA   0.2f

#define NB      16                 // nodes per LSTM block
#define NCHUNK  (N_NODES / NB)     // 256 chunks
#define GP      260                // gates smem pitch (floats)
#define XP      20                 // x/h smem row pitch (floats, 16B-aligned)

typedef unsigned long long ull;

// ------------------------- device scratch (no mallocs allowed) -------------
__device__ float d_Wh [N_NODES * F_OUT];
__device__ float d_Wh2[N_NODES * F_OUT];
__device__ float d_e1 [N_NODES];
__device__ float d_e2 [N_NODES];
__device__ int   d_ord[N_NODES * MAX_DEG];
__device__ int   d_sorted[N_NODES];
__device__ int   d_work;

// ------------------------- K0: Wh = h @ W, fused e1/e2 ---------------------
// grid 128, block 256, dyn smem 96KB
__global__ void k_wh(const float* __restrict__ h, const float* __restrict__ W,
                     const float* __restrict__ a) {
    extern __shared__ float sm[];
    float* Wsm = sm;                       // [256][64]
    float* hsm = sm + F_IN * F_OUT;        // [32][256], reused as Wh stage [32][64]
    __shared__ float a_sm[128];
    const int tid = threadIdx.x;
    const int r0  = blockIdx.x * 32;
    for (int i = tid; i < F_IN * F_OUT; i += 256) Wsm[i] = W[i];
    for (int i = tid; i < 32 * F_IN;    i += 256) hsm[i] = h[(size_t)r0 * F_IN + i];
    if (tid < 128) a_sm[tid] = a[tid];
    __syncthreads();
    const int f  = tid & 63;
    const int rq = tid >> 6;
    float acc[8];
#pragma unroll
    for (int j = 0; j < 8; j++) acc[j] = 0.f;
    for (int k = 0; k < F_IN; k++) {
        const float w = Wsm[k * F_OUT + f];
#pragma unroll
        for (int j = 0; j < 8; j++)
            acc[j] = fmaf(w, hsm[(rq * 8 + j) * F_IN + k], acc[j]);
    }
    __syncthreads();                       // all reads of hsm complete
    float* whs = hsm;                      // reuse: [32][64]
#pragma unroll
    for (int j = 0; j < 8; j++) {
        const int row = rq * 8 + j;
        whs[row * 64 + f] = acc[j];
        d_Wh[(r0 + row) * F_OUT + f] = acc[j];
    }
    __syncthreads();

    // e1/e2: warp w handles rows 4w..4w+3
    const int warp = tid >> 5, lane = tid & 31;
#pragma unroll
    for (int rr = 0; rr < 4; rr++) {
        const int row = warp * 4 + rr;
        const float v0 = whs[row * 64 + lane];
        const float v1 = whs[row * 64 + 32 + lane];
        float s1 = v0 * a_sm[lane]      + v1 * a_sm[lane + 32];
        float s2 = v0 * a_sm[64 + lane] + v1 * a_sm[96 + lane];
#pragma unroll
        for (int o = 16; o; o >>= 1) {
            s1 += __shfl_xor_sync(0xffffffffu, s1, o);
            s2 += __shfl_xor_sync(0xffffffffu, s2, o);
        }
        if (lane == 0) { d_e1[r0 + row] = s1; d_e2[r0 + row] = s2; }
    }
}

// ------------------------- K1: attention per node --------------------------
__global__ void k_att(const float* __restrict__ adj) {
    __shared__ int   nbr[64];
    __shared__ float satt[64];
    __shared__ int   wcnt[8];
    __shared__ int   scnt;
    __shared__ float smax, ssum;
    __shared__ float spart[4][64];

    const int i    = blockIdx.x;
    const int tid  = threadIdx.x;
    const int warp = tid >> 5;
    const int lane = tid & 31;

    if (tid == 0) scnt = 0;
    __syncthreads();

    for (int base = 0; base < N_NODES; base += 256) {
        const float v = adj[(size_t)i * N_NODES + base + tid];
        const unsigned m = __ballot_sync(0xffffffffu, v > 0.f);
        if (lane == 0) wcnt[warp] = __popc(m);
        __syncthreads();
        int pref = scnt;
        for (int w = 0; w < warp; w++) pref += wcnt[w];
        if (v > 0.f) {
            const int pos = pref + __popc(m & ((1u << lane) - 1u));
            if (pos < 64) nbr[pos] = base + tid;
        }
        __syncthreads();
        if (tid == 0) {
            int t = 0;
            for (int w = 0; w < 8; w++) t += wcnt[w];
            scnt += t;
        }
        __syncthreads();
    }
    const int L = (scnt < 64) ? scnt : 64;

    const float e1i = d_e1[i];
    if (tid < L) {
        float ev = e1i + d_e2[nbr[tid]];
        ev = ev > 0.f ? ev : ALPHA * ev;
        satt[tid] = ev;
    }
    __syncthreads();
    if (tid == 0) {
        float mx = satt[0];
        for (int n = 1; n < L; n++) mx = fmaxf(mx, satt[n]);
        smax = mx;
    }
    __syncthreads();
    if (tid < L) satt[tid] = __expf(satt[tid] - smax);
    __syncthreads();
    if (tid == 0) {
        float s = 0.f;
        for (int n = 0; n < L; n++) s += satt[n];
        ssum = s;
    }
    __syncthreads();
    if (tid < L) satt[tid] = satt[tid] / ssum;
    __syncthreads();

    if (tid < L) {
        const float av = satt[tid];
        const int   jv = nbr[tid];
        int rank = 0;
        for (int k = 0; k < L; k++) {
            const float ak = satt[k];
            rank += (ak > av) || (ak == av && nbr[k] < jv);
        }
        d_ord[i * MAX_DEG + rank] = jv;
    }

    const int f = tid & 63, s = tid >> 6;
    float part = 0.f;
    for (int n = s; n < L; n += 4)
        part = fmaf(satt[n], d_Wh[nbr[n] * F_OUT + f], part);
    spart[s][f] = part;
    __syncthreads();
    if (s == 0)
        d_Wh2[i * F_OUT + f] = spart[0][f] + spart[1][f] + spart[2][f] + spart[3][f];
}

// ------------------------- K2: counting sort (single block) ----------------
__global__ void k_sort(const int* __restrict__ sl) {
    __shared__ int hist[64];
    __shared__ int off[64];
    const int t = threadIdx.x;
    if (t < 64) hist[t] = 0;
    if (t == 0) d_work = 0;
    __syncthreads();
    for (int i = t; i < N_NODES; i += 1024) atomicAdd(&hist[64 - sl[i]], 1);
    __syncthreads();
    if (t == 0) {
        int acc = 0;
        for (int b = 0; b < 64; b++) { off[b] = acc; acc += hist[b]; }
    }
    __syncthreads();
    for (int i = t; i < N_NODES; i += 1024) {
        const int p = atomicAdd(&off[64 - sl[i]], 1);
        d_sorted[p] = i;   // intra-bin order nondeterministic; per-node results
                           // are chunk-independent, so final output is deterministic
    }
}

// ------------------------- K3: persistent LSTM -----------------------------
#define LSTM_SMEM_FLOATS (2 * 64 * 256 + 256 + 2 * 64 * XP + 16 * 64 + NB * GP)
#define LSTM_SMEM_BYTES  (LSTM_SMEM_FLOATS * 4 + 64 * 4)

__device__ __forceinline__ ull pack2(float x) {
    ull r; asm("mov.b64 %0, {%1, %1};" : "=l"(r) : "f"(x)); return r;
}
__device__ __forceinline__ void fma2(ull& d, ull a, ull b) {
    asm("fma.rn.f32x2 %0, %1, %2, %0;" : "+l"(d) : "l"(a), "l"(b));
}
__device__ __forceinline__ float2 unpk(ull v) {
    float2 f; asm("mov.b64 {%0, %1}, %2;" : "=f"(f.x), "=f"(f.y) : "l"(v)); return f;
}

// raw approximation MUFU ops — no division subroutine, no Newton fixup
#define LOG2E  1.4426950408889634f
#define LOG2E2 2.8853900817779268f
__device__ __forceinline__ float ex2a(float x) {
    float r; asm("ex2.approx.f32 %0, %1;" : "=f"(r) : "f"(x)); return r;
}
__device__ __forceinline__ float rcpa(float x) {
    float r; asm("rcp.approx.f32 %0, %1;" : "=f"(r) : "f"(x)); return r;
}
__device__ __forceinline__ float sigf(float x) {          // 2 MUFU + 2 flop
    return rcpa(1.f + ex2a(-x * LOG2E));
}
__device__ __forceinline__ float tanhfast(float x) {      // 2 MUFU + 3 flop
    return fmaf(-2.f, rcpa(ex2a(x * LOG2E2) + 1.f), 1.f);
}

__global__ __launch_bounds__(256, 1)
void k_lstm(const float* __restrict__ w_ih, const float* __restrict__ w_hh,
            const float* __restrict__ b_ih, const float* __restrict__ b_hh,
            const int* __restrict__ sl, float* __restrict__ out) {
    extern __shared__ float sm[];
    float* s_wih = sm;                      // [64][256]  k-major (transposed)
    float* s_whh = s_wih + 64 * 256;        // [64][256]
    float* s_b   = s_whh + 64 * 256;        // [256]
    float* x_sm  = s_b + 256;               // [64][XP]
    float* h_sm  = x_sm + 64 * XP;          // [64][XP]
    float* c_sm  = h_sm + 64 * XP;          // [16][64]
    float* g_sm  = c_sm + 16 * 64;          // [16][GP]  node-major gates
    int*   s_node = (int*)(g_sm + NB * GP); // [16]
    int*   s_L    = s_node + NB;            // [16]
    int*   s_meta = s_L + NB;               // [0]=chunk [1]=maxL

    const int tid = threadIdx.x;

    for (int idx = tid; idx < 256 * 64; idx += 256) {
        const int g = idx >> 6, k = idx & 63;
        s_wih[k * 256 + g] = w_ih[idx];
        s_whh[k * 256 + g] = w_hh[idx];
    }
    s_b[tid] = b_ih[tid] + b_hh[tid];
    __syncthreads();   // cross-warp read of s_b below (R4 fix)

    // GEMM mapping: thread owns gates {2*q3, 2*q3+1} for nodes 8*s3 .. 8*s3+7
    const int q3 = tid & 127;
    const int s3 = tid >> 7;
    const float2* wi2 = (const float2*)s_wih;
    const float2* wh2 = (const float2*)s_whh;
    const ull bg0 = pack2(s_b[2 * q3]);
    const ull bg1 = pack2(s_b[2 * q3 + 1]);

    // gather mapping: node gm (low bits -> conflict-free STS), k-chunk gk4
    const int gm  = tid & 15;
    const int gk4 = tid >> 4;

    while (true) {
        __syncthreads();
        if (tid == 0) s_meta[0] = atomicAdd(&d_work, 1);
        __syncthreads();
        const int chunk = s_meta[0];
        if (chunk >= NCHUNK) break;

        if (tid < NB) {
            const int node = d_sorted[chunk * NB + tid];
            s_node[tid] = node;
            s_L[tid]    = sl[node];
        }
        for (int idx = tid; idx < 64 * XP; idx += 256) h_sm[idx] = 0.f;
        for (int idx = tid; idx < 16 * 64; idx += 256) c_sm[idx] = 0.f;
        __syncthreads();
        if (tid == 0) {
            int mx = 0;
            for (int m = 0; m < NB; m++) mx = max(mx, s_L[m]);
            s_meta[1] = mx;
        }
        __syncthreads();
        const int maxL = s_meta[1];
        const int Lg   = s_L[gm];
        const int obase = s_node[gm] * MAX_DEG;

        // prefetch x for t=0
        float4 xv;
        {
            int idx = Lg - 1; if (idx < 0) idx = 0;
            const int row = d_ord[obase + idx];
            xv = *(const float4*)(&d_Wh2[row * F_OUT + gk4 * 4]);
        }

        for (int t = 0; t < maxL; t++) {
            // phase A: write x(t); state update for step t-1
            x_sm[(gk4 * 4 + 0) * XP + gm] = xv.x;
            x_sm[(gk4 * 4 + 1) * XP + gm] = xv.y;
            x_sm[(gk4 * 4 + 2) * XP + gm] = xv.z;
            x_sm[(gk4 * 4 + 3) * XP + gm] = xv.w;
            if (t + 1 < maxL) {
                int idx = Lg - 2 - t; if (idx < 0) idx = 0;
                const int row = d_ord[obase + idx];
                xv = *(const float4*)(&d_Wh2[row * F_OUT + gk4 * 4]);
            }
            if (t > 0) {
#pragma unroll
                for (int rep = 0; rep < 4; rep++) {
                    const int idx = tid + rep * 256;
                    const int u = idx & 63, m = idx >> 6;
                    if (t - 1 < s_L[m]) {
                        const float gi = g_sm[m * GP + u];
                        const float gf = g_sm[m * GP + 64 + u];
                        const float gg = g_sm[m * GP + 128 + u];
                        const float go = g_sm[m * GP + 192 + u];
                        const float c  = c_sm[m * 64 + u];
                        const float cn = sigf(gf) * c + sigf(gi) * tanhfast(gg);
                        const float hn = sigf(go) * tanhfast(cn);
                        c_sm[m * 64 + u] = cn;
                        h_sm[u * XP + m] = hn;
                    }
                }
            }
            __syncthreads();

            // phase B: gate GEMM, f32x2 packed over adjacent node pairs
            ull a00 = bg0, a01 = bg0, a02 = bg0, a03 = bg0;
            ull a10 = bg1, a11 = bg1, a12 = bg1, a13 = bg1;
#pragma unroll 4
            for (int k = 0; k < 64; k++) {
                const float2 wi = wi2[k * 128 + q3];
                const float2 wh = wh2[k * 128 + q3];
                const ull wi0 = pack2(wi.x), wi1 = pack2(wi.y);
                const ull wh0 = pack2(wh.x), wh1 = pack2(wh.y);
                const ulonglong2 xa = *(const ulonglong2*)(x_sm + k * XP + 8 * s3);
                const ulonglong2 xb = *(const ulonglong2*)(x_sm + k * XP + 8 * s3 + 4);
                const ulonglong2 ha = *(const ulonglong2*)(h_sm + k * XP + 8 * s3);
                const ulonglong2 hb = *(const ulonglong2*)(h_sm + k * XP + 8 * s3 + 4);
                fma2(a00, wi0, xa.x); fma2(a01, wi0, xa.y);
                fma2(a02, wi0, xb.x); fma2(a03, wi0, xb.y);
                fma2(a10, wi1, xa.x); fma2(a11, wi1, xa.y);
                fma2(a12, wi1, xb.x); fma2(a13, wi1, xb.y);
                fma2(a00, wh0, ha.x); fma2(a01, wh0, ha.y);
                fma2(a02, wh0, hb.x); fma2(a03, wh0, hb.y);
                fma2(a10, wh1, ha.x); fma2(a11, wh1, ha.y);
                fma2(a12, wh1, hb.x); fma2(a13, wh1, hb.y);
            }
            {
                const int nb0 = 8 * s3;
                const float2 p00 = unpk(a00), p10 = unpk(a10);
                const float2 p01 = unpk(a01), p11 = unpk(a11);
                const float2 p02 = unpk(a02), p12 = unpk(a12);
                const float2 p03 = unpk(a03), p13 = unpk(a13);
                float* gq = g_sm + 2 * q3;
                *(float2*)(gq + (nb0 + 0) * GP) = make_float2(p00.x, p10.x);
                *(float2*)(gq + (nb0 + 1) * GP) = make_float2(p00.y, p10.y);
                *(float2*)(gq + (nb0 + 2) * GP) = make_float2(p01.x, p11.x);
                *(float2*)(gq + (nb0 + 3) * GP) = make_float2(p01.y, p11.y);
                *(float2*)(gq + (nb0 + 4) * GP) = make_float2(p02.x, p12.x);
                *(float2*)(gq + (nb0 + 5) * GP) = make_float2(p02.y, p12.y);
                *(float2*)(gq + (nb0 + 6) * GP) = make_float2(p03.x, p13.x);
                *(float2*)(gq + (nb0 + 7) * GP) = make_float2(p03.y, p13.y);
            }
            __syncthreads();
        }

        // final update for step maxL-1
#pragma unroll
        for (int rep = 0; rep < 4; rep++) {
            const int idx = tid + rep * 256;
            const int u = idx & 63, m = idx >> 6;
            if (maxL - 1 < s_L[m]) {
                const float gi = g_sm[m * GP + u];
                const float gf = g_sm[m * GP + 64 + u];
                const float gg = g_sm[m * GP + 128 + u];
                const float go = g_sm[m * GP + 192 + u];
                const float c  = c_sm[m * 64 + u];
                const float cn = sigf(gf) * c + sigf(gi) * tanhfast(gg);
                const float hn = sigf(go) * tanhfast(cn);
                c_sm[m * 64 + u] = cn;
                h_sm[u * XP + m] = hn;
            }
        }
        __syncthreads();

        // write hn
#pragma unroll
        for (int rep = 0; rep < 4; rep++) {
            const int idx = tid + rep * 256;
            const int u = idx & 63, m = idx >> 6;
            out[s_node[m] * HDIM + u] = h_sm[u * XP + m];
        }
    }
}

// ------------------------- launch ------------------------------------------
extern "C" void kernel_launch(void* const* d_in, const int* in_sizes, int n_in,
                              void* d_out, int out_size) {
    const float* h   = (const float*)d_in[0];
    const float* adj = (const float*)d_in[1];
    const int*   sl  = (const int*)  d_in[2];
    const float* W   = (const float*)d_in[3];
    const float* a   = (const float*)d_in[4];
    const float* wih = (const float*)d_in[5];
    const float* whh = (const float*)d_in[6];
    const float* bih = (const float*)d_in[7];
    const float* bhh = (const float*)d_in[8];
    float* out = (float*)d_out;

    cudaFuncSetAttribute(k_wh,   cudaFuncAttributeMaxDynamicSharedMemorySize, 96 * 1024);
    cudaFuncSetAttribute(k_lstm, cudaFuncAttributeMaxDynamicSharedMemorySize, LSTM_SMEM_BYTES);

    int sms = 148;
    cudaDeviceGetAttribute(&sms, cudaDevAttrMultiProcessorCount, 0);

    // k_lstm is my launch index 3: with the 2 harness pre-launches, ncu -s 5
    // lands exactly on it.
    k_wh  <<<128,  256, 96 * 1024>>>(h, W, a);                           // 0
    k_att <<<4096, 256>>>(adj);                                          // 1
    k_sort<<<1,   1024>>>(sl);                                           // 2
    k_lstm<<<sms,  256, LSTM_SMEM_BYTES>>>(wih, whh, bih, bhh, sl, out); // 3
}

// round 12
// speedup vs baseline: 1.2958x; 1.0002x over previous
#include <cuda_runtime.h>
#include <cstdint>

#define N_NODES 4096
#define F_IN    256
#define F_OUT   64
#define HDIM    64
#define MAX_DEG 64
#define ALPHA   0.2f

#define NB      16                 // nodes per LSTM block
#define NCHUNK  (N_NODES / NB)     // 256 chunks
#define GP      260                // gates smem pitch (floats)
#define XP      20                 // x/h smem row pitch (floats, 16B-aligned)

typedef unsigned long long ull;

// ------------------------- device scratch (no mallocs allowed) -------------
__device__ float d_Wh [N_NODES * F_OUT];
__device__ float d_Wh2[N_NODES * F_OUT];
__device__ float d_e1 [N_NODES];
__device__ float d_e2 [N_NODES];
__device__ int   d_ord[N_NODES * MAX_DEG];
__device__ int   d_sorted[N_NODES];
__device__ int   d_work;

// ------------------------- K0: Wh = h @ W, fused e1/e2 ---------------------
// grid 128, block 256, dyn smem 96KB
__global__ void k_wh(const float* __restrict__ h, const float* __restrict__ W,
                     const float* __restrict__ a) {
    extern __shared__ float sm[];
    float* Wsm = sm;                       // [256][64]
    float* hsm = sm + F_IN * F_OUT;        // [32][256], reused as Wh stage [32][64]
    __shared__ float a_sm[128];
    const int tid = threadIdx.x;
    const int r0  = blockIdx.x * 32;
    for (int i = tid; i < F_IN * F_OUT; i += 256) Wsm[i] = W[i];
    for (int i = tid; i < 32 * F_IN;    i += 256) hsm[i] = h[(size_t)r0 * F_IN + i];
    if (tid < 128) a_sm[tid] = a[tid];
    __syncthreads();
    const int f  = tid & 63;
    const int rq = tid >> 6;
    float acc[8];
#pragma unroll
    for (int j = 0; j < 8; j++) acc[j] = 0.f;
    for (int k = 0; k < F_IN; k++) {
        const float w = Wsm[k * F_OUT + f];
#pragma unroll
        for (int j = 0; j < 8; j++)
            acc[j] = fmaf(w, hsm[(rq * 8 + j) * F_IN + k], acc[j]);
    }
    __syncthreads();                       // all reads of hsm complete
    float* whs = hsm;                      // reuse: [32][64]
#pragma unroll
    for (int j = 0; j < 8; j++) {
        const int row = rq * 8 + j;
        whs[row * 64 + f] = acc[j];
        d_Wh[(r0 + row) * F_OUT + f] = acc[j];
    }
    __syncthreads();

    // e1/e2: warp w handles rows 4w..4w+3
    const int warp = tid >> 5, lane = tid & 31;
#pragma unroll
    for (int rr = 0; rr < 4; rr++) {
        const int row = warp * 4 + rr;
        const float v0 = whs[row * 64 + lane];
        const float v1 = whs[row * 64 + 32 + lane];
        float s1 = v0 * a_sm[lane]      + v1 * a_sm[lane + 32];
        float s2 = v0 * a_sm[64 + lane] + v1 * a_sm[96 + lane];
#pragma unroll
        for (int o = 16; o; o >>= 1) {
            s1 += __shfl_xor_sync(0xffffffffu, s1, o);
            s2 += __shfl_xor_sync(0xffffffffu, s2, o);
        }
        if (lane == 0) { d_e1[r0 + row] = s1; d_e2[r0 + row] = s2; }
    }
}

// ------------------------- K1: attention per node --------------------------
__global__ void k_att(const float* __restrict__ adj) {
    __shared__ int   nbr[64];
    __shared__ float satt[64];
    __shared__ int   wcnt[8];
    __shared__ int   scnt;
    __shared__ float smax, ssum;
    __shared__ float spart[4][64];

    const int i    = blockIdx.x;
    const int tid  = threadIdx.x;
    const int warp = tid >> 5;
    const int lane = tid & 31;

    if (tid == 0) scnt = 0;
    __syncthreads();

    for (int base = 0; base < N_NODES; base += 256) {
        const float v = adj[(size_t)i * N_NODES + base + tid];
        const unsigned m = __ballot_sync(0xffffffffu, v > 0.f);
        if (lane == 0) wcnt[warp] = __popc(m);
        __syncthreads();
        int pref = scnt;
        for (int w = 0; w < warp; w++) pref += wcnt[w];
        if (v > 0.f) {
            const int pos = pref + __popc(m & ((1u << lane) - 1u));
            if (pos < 64) nbr[pos] = base + tid;
        }
        __syncthreads();
        if (tid == 0) {
            int t = 0;
            for (int w = 0; w < 8; w++) t += wcnt[w];
            scnt += t;
        }
        __syncthreads();
    }
    const int L = (scnt < 64) ? scnt : 64;

    const float e1i = d_e1[i];
    if (tid < L) {
        float ev = e1i + d_e2[nbr[tid]];
        ev = ev > 0.f ? ev : ALPHA * ev;
        satt[tid] = ev;
    }
    __syncthreads();
    if (tid == 0) {
        float mx = satt[0];
        for (int n = 1; n < L; n++) mx = fmaxf(mx, satt[n]);
        smax = mx;
    }
    __syncthreads();
    if (tid < L) satt[tid] = __expf(satt[tid] - smax);
    __syncthreads();
    if (tid == 0) {
        float s = 0.f;
        for (int n = 0; n < L; n++) s += satt[n];
        ssum = s;
    }
    __syncthreads();
    if (tid < L) satt[tid] = satt[tid] / ssum;
    __syncthreads();

    if (tid < L) {
        const float av = satt[tid];
        const int   jv = nbr[tid];
        int rank = 0;
        for (int k = 0; k < L; k++) {
            const float ak = satt[k];
            rank += (ak > av) || (ak == av && nbr[k] < jv);
        }
        d_ord[i * MAX_DEG + rank] = jv;
    }

    const int f = tid & 63, s = tid >> 6;
    float part = 0.f;
    for (int n = s; n < L; n += 4)
        part = fmaf(satt[n], d_Wh[nbr[n] * F_OUT + f], part);
    spart[s][f] = part;
    __syncthreads();
    if (s == 0)
        d_Wh2[i * F_OUT + f] = spart[0][f] + spart[1][f] + spart[2][f] + spart[3][f];
}

// ------------------------- K2: counting sort (single block) ----------------
__global__ void k_sort(const int* __restrict__ sl) {
    __shared__ int hist[64];
    __shared__ int off[64];
    const int t = threadIdx.x;
    if (t < 64) hist[t] = 0;
    if (t == 0) d_work = 0;
    __syncthreads();
    for (int i = t; i < N_NODES; i += 1024) atomicAdd(&hist[64 - sl[i]], 1);
    __syncthreads();
    if (t == 0) {
        int acc = 0;
        for (int b = 0; b < 64; b++) { off[b] = acc; acc += hist[b]; }
    }
    __syncthreads();
    for (int i = t; i < N_NODES; i += 1024) {
        const int p = atomicAdd(&off[64 - sl[i]], 1);
        d_sorted[p] = i;   // intra-bin order nondeterministic; per-node results
                           // are chunk-independent, so final output is deterministic
    }
}

// ------------------------- K3: persistent LSTM -----------------------------
#define LSTM_SMEM_FLOATS (2 * 64 * 256 + 256 + 2 * 64 * XP + 16 * 64 + NB * GP)
#define LSTM_SMEM_BYTES  (LSTM_SMEM_FLOATS * 4 + 64 * 4)

__device__ __forceinline__ ull pack2(float x) {
    ull r; asm("mov.b64 %0, {%1, %1};" : "=l"(r) : "f"(x)); return r;
}
__device__ __forceinline__ void fma2(ull& d, ull a, ull b) {
    asm("fma.rn.f32x2 %0, %1, %2, %0;" : "+l"(d) : "l"(a), "l"(b));
}
__device__ __forceinline__ float2 unpk(ull v) {
    float2 f; asm("mov.b64 {%0, %1}, %2;" : "=f"(f.x), "=f"(f.y) : "l"(v)); return f;
}

// raw approximation MUFU ops — no division subroutine, no Newton fixup
#define LOG2E  1.4426950408889634f
#define LOG2E2 2.8853900817779268f
__device__ __forceinline__ float ex2a(float x) {
    float r; asm("ex2.approx.f32 %0, %1;" : "=f"(r) : "f"(x)); return r;
}
__device__ __forceinline__ float rcpa(float x) {
    float r; asm("rcp.approx.f32 %0, %1;" : "=f"(r) : "f"(x)); return r;
}
__device__ __forceinline__ float sigf(float x) {          // 2 MUFU + 2 flop
    return rcpa(1.f + ex2a(-x * LOG2E));
}
__device__ __forceinline__ float tanhfast(float x) {      // 2 MUFU + 3 flop
    return fmaf(-2.f, rcpa(ex2a(x * LOG2E2) + 1.f), 1.f);
}

__global__ __launch_bounds__(256, 1)
void k_lstm(const float* __restrict__ w_ih, const float* __restrict__ w_hh,
            const float* __restrict__ b_ih, const float* __restrict__ b_hh,
            const int* __restrict__ sl, float* __restrict__ out) {
    extern __shared__ float sm[];
    float* s_wih = sm;                      // [64][256]  k-major (transposed)
    float* s_whh = s_wih + 64 * 256;        // [64][256]
    float* s_b   = s_whh + 64 * 256;        // [256]
    float* x_sm  = s_b + 256;               // [64][XP]
    float* h_sm  = x_sm + 64 * XP;          // [64][XP]
    float* c_sm  = h_sm + 64 * XP;          // [16][64]
    float* g_sm  = c_sm + 16 * 64;          // [16][GP]  node-major gates
    int*   s_node = (int*)(g_sm + NB * GP); // [16]
    int*   s_L    = s_node + NB;            // [16]
    int*   s_meta = s_L + NB;               // [0]=chunk [1]=maxL

    const int tid = threadIdx.x;

    for (int idx = tid; idx < 256 * 64; idx += 256) {
        const int g = idx >> 6, k = idx & 63;
        s_wih[k * 256 + g] = w_ih[idx];
        s_whh[k * 256 + g] = w_hh[idx];
    }
    s_b[tid] = b_ih[tid] + b_hh[tid];
    __syncthreads();   // cross-warp read of s_b below (R4 fix)

    // GEMM mapping: thread owns gates {2*q3, 2*q3+1} for nodes 8*s3 .. 8*s3+7
    const int q3 = tid & 127;
    const int s3 = tid >> 7;
    const float2* wi2 = (const float2*)s_wih;
    const float2* wh2 = (const float2*)s_whh;
    const ull bg0 = pack2(s_b[2 * q3]);
    const ull bg1 = pack2(s_b[2 * q3 + 1]);

    // gather mapping: node gm (low bits -> conflict-free STS), k-chunk gk4
    const int gm  = tid & 15;
    const int gk4 = tid >> 4;

    while (true) {
        __syncthreads();
        if (tid == 0) s_meta[0] = atomicAdd(&d_work, 1);
        __syncthreads();
        const int chunk = s_meta[0];
        if (chunk >= NCHUNK) break;

        if (tid < NB) {
            const int node = d_sorted[chunk * NB + tid];
            s_node[tid] = node;
            s_L[tid]    = sl[node];
        }
        for (int idx = tid; idx < 64 * XP; idx += 256) h_sm[idx] = 0.f;
        for (int idx = tid; idx < 16 * 64; idx += 256) c_sm[idx] = 0.f;
        __syncthreads();
        if (tid == 0) {
            int mx = 0;
            for (int m = 0; m < NB; m++) mx = max(mx, s_L[m]);
            s_meta[1] = mx;
        }
        __syncthreads();
        const int maxL = s_meta[1];
        const int Lg   = s_L[gm];
        const int obase = s_node[gm] * MAX_DEG;

        // prefetch x for t=0
        float4 xv;
        {
            int idx = Lg - 1; if (idx < 0) idx = 0;
            const int row = d_ord[obase + idx];
            xv = *(const float4*)(&d_Wh2[row * F_OUT + gk4 * 4]);
        }

        for (int t = 0; t < maxL; t++) {
            // phase A: write x(t); state update for step t-1
            x_sm[(gk4 * 4 + 0) * XP + gm] = xv.x;
            x_sm[(gk4 * 4 + 1) * XP + gm] = xv.y;
            x_sm[(gk4 * 4 + 2) * XP + gm] = xv.z;
            x_sm[(gk4 * 4 + 3) * XP + gm] = xv.w;
            if (t + 1 < maxL) {
                int idx = Lg - 2 - t; if (idx < 0) idx = 0;
                const int row = d_ord[obase + idx];
                xv = *(const float4*)(&d_Wh2[row * F_OUT + gk4 * 4]);
            }
            if (t > 0) {
#pragma unroll
                for (int rep = 0; rep < 4; rep++) {
                    const int idx = tid + rep * 256;
                    const int u = idx & 63, m = idx >> 6;
                    if (t - 1 < s_L[m]) {
                        const float gi = g_sm[m * GP + u];
                        const float gf = g_sm[m * GP + 64 + u];
                        const float gg = g_sm[m * GP + 128 + u];
                        const float go = g_sm[m * GP + 192 + u];
                        const float c  = c_sm[m * 64 + u];
                        const float cn = sigf(gf) * c + sigf(gi) * tanhfast(gg);
                        const float hn = sigf(go) * tanhfast(cn);
                        c_sm[m * 64 + u] = cn;
                        h_sm[u * XP + m] = hn;
                    }
                }
            }
            __syncthreads();

            // phase B: gate GEMM, f32x2 packed over adjacent node pairs
            ull a00 = bg0, a01 = bg0, a02 = bg0, a03 = bg0;
            ull a10 = bg1, a11 = bg1, a12 = bg1, a13 = bg1;
#pragma unroll 4
            for (int k = 0; k < 64; k++) {
                const float2 wi = wi2[k * 128 + q3];
                const float2 wh = wh2[k * 128 + q3];
                const ull wi0 = pack2(wi.x), wi1 = pack2(wi.y);
                const ull wh0 = pack2(wh.x), wh1 = pack2(wh.y);
                const ulonglong2 xa = *(const ulonglong2*)(x_sm + k * XP + 8 * s3);
                const ulonglong2 xb = *(const ulonglong2*)(x_sm + k * XP + 8 * s3 + 4);
                const ulonglong2 ha = *(const ulonglong2*)(h_sm + k * XP + 8 * s3);
                const ulonglong2 hb = *(const ulonglong2*)(h_sm + k * XP + 8 * s3 + 4);
                fma2(a00, wi0, xa.x); fma2(a01, wi0, xa.y);
                fma2(a02, wi0, xb.x); fma2(a03, wi0, xb.y);
                fma2(a10, wi1, xa.x); fma2(a11, wi1, xa.y);
                fma2(a12, wi1, xb.x); fma2(a13, wi1, xb.y);
                fma2(a00, wh0, ha.x); fma2(a01, wh0, ha.y);
                fma2(a02, wh0, hb.x); fma2(a03, wh0, hb.y);
                fma2(a10, wh1, ha.x); fma2(a11, wh1, ha.y);
                fma2(a12, wh1, hb.x); fma2(a13, wh1, hb.y);
            }
            {
                const int nb0 = 8 * s3;
                const float2 p00 = unpk(a00), p10 = unpk(a10);
                const float2 p01 = unpk(a01), p11 = unpk(a11);
                const float2 p02 = unpk(a02), p12 = unpk(a12);
                const float2 p03 = unpk(a03), p13 = unpk(a13);
                float* gq = g_sm + 2 * q3;
                *(float2*)(gq + (nb0 + 0) * GP) = make_float2(p00.x, p10.x);
                *(float2*)(gq + (nb0 + 1) * GP) = make_float2(p00.y, p10.y);
                *(float2*)(gq + (nb0 + 2) * GP) = make_float2(p01.x, p11.x);
                *(float2*)(gq + (nb0 + 3) * GP) = make_float2(p01.y, p11.y);
                *(float2*)(gq + (nb0 + 4) * GP) = make_float2(p02.x, p12.x);
                *(float2*)(gq + (nb0 + 5) * GP) = make_float2(p02.y, p12.y);
                *(float2*)(gq + (nb0 + 6) * GP) = make_float2(p03.x, p13.x);
                *(float2*)(gq + (nb0 + 7) * GP) = make_float2(p03.y, p13.y);
            }
            __syncthreads();
        }

        // final update for step maxL-1
#pragma unroll
        for (int rep = 0; rep < 4; rep++) {
            const int idx = tid + rep * 256;
            const int u = idx & 63, m = idx >> 6;
            if (maxL - 1 < s_L[m]) {
                const float gi = g_sm[m * GP + u];
                const float gf = g_sm[m * GP + 64 + u];
                const float gg = g_sm[m * GP + 128 + u];
                const float go = g_sm[m * GP + 192 + u];
                const float c  = c_sm[m * 64 + u];
                const float cn = sigf(gf) * c + sigf(gi) * tanhfast(gg);
                const float hn = sigf(go) * tanhfast(cn);
                c_sm[m * 64 + u] = cn;
                h_sm[u * XP + m] = hn;
            }
        }
        __syncthreads();

        // write hn
#pragma unroll
        for (int rep = 0; rep < 4; rep++) {
            const int idx = tid + rep * 256;
            const int u = idx & 63, m = idx >> 6;
            out[s_node[m] * HDIM + u] = h_sm[u * XP + m];
        }
    }
}

// ------------------------- launch ------------------------------------------
extern "C" void kernel_launch(void* const* d_in, const int* in_sizes, int n_in,
                              void* d_out, int out_size) {
    const float* h   = (const float*)d_in[0];
    const float* adj = (const float*)d_in[1];
    const int*   sl  = (const int*)  d_in[2];
    const float* W   = (const float*)d_in[3];
    const float* a   = (const float*)d_in[4];
    const float* wih = (const float*)d_in[5];
    const float* whh = (const float*)d_in[6];
    const float* bih = (const float*)d_in[7];
    const float* bhh = (const float*)d_in[8];
    float* out = (float*)d_out;

    cudaFuncSetAttribute(k_wh,   cudaFuncAttributeMaxDynamicSharedMemorySize, 96 * 1024);
    cudaFuncSetAttribute(k_lstm, cudaFuncAttributeMaxDynamicSharedMemorySize, LSTM_SMEM_BYTES);

    int sms = 148;
    cudaDeviceGetAttribute(&sms, cudaDevAttrMultiProcessorCount, 0);

    // k_lstm is my launch index 3: with the 2 harness pre-launches, ncu -s 5
    // lands exactly on it.
    k_wh  <<<128,  256, 96 * 1024>>>(h, W, a);                           // 0
    k_att <<<4096, 256>>>(adj);                                          // 1
    k_sort<<<1,   1024>>>(sl);                                           // 2
    k_lstm<<<sms,  256, LSTM_SMEM_BYTES>>>(wih, whh, bih, bhh, sl, out); // 3
}

// round 13
// speedup vs baseline: 1.4596x; 1.1264x over previous
#include <cuda_runtime.h>
#include <cstdint>

#define N_NODES 4096
#define F_IN    256
#define F_OUT   64
#define HDIM    64
#define MAX_DEG 64
#define ALPHA   0.2f

#define NB      16                 // nodes per LSTM block
#define NCHUNK  (N_NODES / NB)     // 256 chunks
#define GP      260                // gates smem pitch (floats)
#define XP      20                 // x/h smem row pitch (floats, 16B-aligned)

typedef unsigned long long ull;

// ------------------------- device scratch (no mallocs allowed) -------------
__device__ float d_Wh [N_NODES * F_OUT];
__device__ float d_Wh2[N_NODES * F_OUT];
__device__ float d_e1 [N_NODES];
__device__ float d_e2 [N_NODES];
__device__ int   d_ord[N_NODES * MAX_DEG];
__device__ int   d_sorted[N_NODES];

// ------------------------- K0: Wh = h @ W, fused e1/e2 ---------------------
__global__ void k_wh(const float* __restrict__ h, const float* __restrict__ W,
                     const float* __restrict__ a) {
    extern __shared__ float sm[];
    float* Wsm = sm;                       // [256][64]
    float* hsm = sm + F_IN * F_OUT;        // [32][256], reused as Wh stage
    __shared__ float a_sm[128];
    const int tid = threadIdx.x;
    const int r0  = blockIdx.x * 32;
    for (int i = tid; i < F_IN * F_OUT; i += 256) Wsm[i] = W[i];
    for (int i = tid; i < 32 * F_IN;    i += 256) hsm[i] = h[(size_t)r0 * F_IN + i];
    if (tid < 128) a_sm[tid] = a[tid];
    __syncthreads();
    const int f  = tid & 63;
    const int rq = tid >> 6;
    float acc[8];
#pragma unroll
    for (int j = 0; j < 8; j++) acc[j] = 0.f;
    for (int k = 0; k < F_IN; k++) {
        const float w = Wsm[k * F_OUT + f];
#pragma unroll
        for (int j = 0; j < 8; j++)
            acc[j] = fmaf(w, hsm[(rq * 8 + j) * F_IN + k], acc[j]);
    }
    __syncthreads();
    float* whs = hsm;                      // reuse: [32][64]
#pragma unroll
    for (int j = 0; j < 8; j++) {
        const int row = rq * 8 + j;
        whs[row * 64 + f] = acc[j];
        d_Wh[(r0 + row) * F_OUT + f] = acc[j];
    }
    __syncthreads();

    const int warp = tid >> 5, lane = tid & 31;
#pragma unroll
    for (int rr = 0; rr < 4; rr++) {
        const int row = warp * 4 + rr;
        const float v0 = whs[row * 64 + lane];
        const float v1 = whs[row * 64 + 32 + lane];
        float s1 = v0 * a_sm[lane]      + v1 * a_sm[lane + 32];
        float s2 = v0 * a_sm[64 + lane] + v1 * a_sm[96 + lane];
#pragma unroll
        for (int o = 16; o; o >>= 1) {
            s1 += __shfl_xor_sync(0xffffffffu, s1, o);
            s2 += __shfl_xor_sync(0xffffffffu, s2, o);
        }
        if (lane == 0) { d_e1[r0 + row] = s1; d_e2[r0 + row] = s2; }
    }
}

// ------------------------- K1: attention per node (low-barrier) ------------
__global__ void k_att(const float* __restrict__ adj) {
    __shared__ int   nbr[64];
    __shared__ float satt[64];
    __shared__ int   wsum[8];
    __shared__ float smax, ssum;
    __shared__ float spart[4][64];

    const int i    = blockIdx.x;
    const int tid  = threadIdx.x;
    const int warp = tid >> 5;
    const int lane = tid & 31;

    // thread-local scan of 16 contiguous columns (4 x float4, MLP=4)
    const float4* row = (const float4*)(adj + (size_t)i * N_NODES);
    float4 v[4];
#pragma unroll
    for (int j = 0; j < 4; j++) v[j] = row[tid * 4 + j];
    int cnt = 0;
#pragma unroll
    for (int j = 0; j < 4; j++)
        cnt += (v[j].x > 0.f) + (v[j].y > 0.f) + (v[j].z > 0.f) + (v[j].w > 0.f);

    // warp inclusive scan of counts
    int incl = cnt;
#pragma unroll
    for (int o = 1; o < 32; o <<= 1) {
        const int nv = __shfl_up_sync(0xffffffffu, incl, o);
        if (lane >= o) incl += nv;
    }
    if (lane == 31) wsum[warp] = incl;
    __syncthreads();
    int woff = 0, total = 0;
#pragma unroll
    for (int w = 0; w < 8; w++) {
        const int c = wsum[w];
        if (w < warp) woff += c;
        total += c;
    }
    int pos = woff + incl - cnt;          // exclusive prefix, ascending in column

#pragma unroll
    for (int j = 0; j < 4; j++) {
        const int c0 = tid * 16 + j * 4;
        if (v[j].x > 0.f) { if (pos < 64) nbr[pos] = c0;     pos++; }
        if (v[j].y > 0.f) { if (pos < 64) nbr[pos] = c0 + 1; pos++; }
        if (v[j].z > 0.f) { if (pos < 64) nbr[pos] = c0 + 2; pos++; }
        if (v[j].w > 0.f) { if (pos < 64) nbr[pos] = c0 + 3; pos++; }
    }
    __syncthreads();
    const int L = (total < 64) ? total : 64;

    const float e1i = d_e1[i];
    if (tid < L) {
        float ev = e1i + d_e2[nbr[tid]];
        ev = ev > 0.f ? ev : ALPHA * ev;
        satt[tid] = ev;
    }
    __syncthreads();
    if (tid == 0) {
        float mx = satt[0];
        for (int n = 1; n < L; n++) mx = fmaxf(mx, satt[n]);
        smax = mx;
    }
    __syncthreads();
    if (tid < L) satt[tid] = __expf(satt[tid] - smax);
    __syncthreads();
    if (tid == 0) {
        float s = 0.f;
        for (int n = 0; n < L; n++) s += satt[n];
        ssum = s;
    }
    __syncthreads();
    if (tid < L) satt[tid] = satt[tid] / ssum;
    __syncthreads();

    // stable rank matching jnp.argsort(-att): desc att, ties -> lower j first
    if (tid < L) {
        const float av = satt[tid];
        const int   jv = nbr[tid];
        int rank = 0;
        for (int k = 0; k < L; k++) {
            const float ak = satt[k];
            rank += (ak > av) || (ak == av && nbr[k] < jv);
        }
        d_ord[i * MAX_DEG + rank] = jv;
    }

    const int f = tid & 63, s = tid >> 6;
    float part = 0.f;
    for (int n = s; n < L; n += 4)
        part = fmaf(satt[n], d_Wh[nbr[n] * F_OUT + f], part);
    spart[s][f] = part;
    __syncthreads();
    if (s == 0)
        d_Wh2[i * F_OUT + f] = spart[0][f] + spart[1][f] + spart[2][f] + spart[3][f];
}

// ------------------------- K2: counting sort (single block) ----------------
__global__ void k_sort(const int* __restrict__ sl) {
    __shared__ int hist[64];
    __shared__ int off[64];
    const int t = threadIdx.x;
    if (t < 64) hist[t] = 0;
    __syncthreads();
    for (int i = t; i < N_NODES; i += 1024) atomicAdd(&hist[64 - sl[i]], 1);
    __syncthreads();
    if (t == 0) {
        int acc = 0;
        for (int b = 0; b < 64; b++) { off[b] = acc; acc += hist[b]; }
    }
    __syncthreads();
    for (int i = t; i < N_NODES; i += 1024) {
        const int p = atomicAdd(&off[64 - sl[i]], 1);
        d_sorted[p] = i;   // intra-bin order nondeterministic; per-node results
                           // are chunk-independent, so final output is deterministic
    }
}

// ------------------------- K3: persistent LSTM (split-k, f32x2) ------------
// SMEM floats: w 32768 + b 256 + x 1280 + h 1280 + c 1024 + gA 4160 + gB 4160
#define LSTM_SMEM_FLOATS (64 * 128 * 4 + 256 + 2 * 64 * XP + 16 * 64 + 2 * NB * GP)
#define LSTM_SMEM_BYTES  (LSTM_SMEM_FLOATS * 4 + 64 * 4)

__device__ __forceinline__ ull pack2(float x) {
    ull r; asm("mov.b64 %0, {%1, %1};" : "=l"(r) : "f"(x)); return r;
}
__device__ __forceinline__ void fma2(ull& d, ull a, ull b) {
    asm("fma.rn.f32x2 %0, %1, %2, %0;" : "+l"(d) : "l"(a), "l"(b));
}
__device__ __forceinline__ float2 unpk(ull v) {
    float2 f; asm("mov.b64 {%0, %1}, %2;" : "=f"(f.x), "=f"(f.y) : "l"(v)); return f;
}

#define LOG2E  1.4426950408889634f
#define LOG2E2 2.8853900817779268f
__device__ __forceinline__ float ex2a(float x) {
    float r; asm("ex2.approx.f32 %0, %1;" : "=f"(r) : "f"(x)); return r;
}
__device__ __forceinline__ float rcpa(float x) {
    float r; asm("rcp.approx.f32 %0, %1;" : "=f"(r) : "f"(x)); return r;
}
__device__ __forceinline__ float sigf(float x) {
    return rcpa(1.f + ex2a(-x * LOG2E));
}
__device__ __forceinline__ float tanhfast(float x) {
    return fmaf(-2.f, rcpa(ex2a(x * LOG2E2) + 1.f), 1.f);
}

__global__ __launch_bounds__(256, 1)
void k_lstm(const float* __restrict__ w_ih, const float* __restrict__ w_hh,
            const float* __restrict__ b_ih, const float* __restrict__ b_hh,
            const int* __restrict__ sl, float* __restrict__ out) {
    extern __shared__ float sm[];
    float* s_w   = sm;                      // [64][128] float4 {wi0,wi1,wh0,wh1}
    float* s_b   = s_w + 64 * 128 * 4;      // [256]
    float* x_sm  = s_b + 256;               // [64][XP]
    float* h_sm  = x_sm + 64 * XP;          // [64][XP]
    float* c_sm  = h_sm + 64 * XP;          // [16][64]
    float* g_a   = c_sm + 16 * 64;          // [16][GP] k-half-0 partials
    float* g_b   = g_a + NB * GP;           // [16][GP] k-half-1 partials
    int*   s_node = (int*)(g_b + NB * GP);  // [16]
    int*   s_L    = s_node + NB;            // [16]
    int*   s_meta = s_L + NB;               // [0]=maxL

    const int tid = threadIdx.x;

    // interleaved weight layout: per (k, gate-pair q) one float4
    for (int idx = tid; idx < 64 * 128; idx += 256) {
        const int k = idx >> 7, q = idx & 127;
        ((float4*)s_w)[idx] = make_float4(
            w_ih[(2 * q) * 64 + k], w_ih[(2 * q + 1) * 64 + k],
            w_hh[(2 * q) * 64 + k], w_hh[(2 * q + 1) * 64 + k]);
    }
    s_b[tid] = b_ih[tid] + b_hh[tid];

    // GEMM mapping: thread = (gate pair q3, k-half kh); covers all 16 nodes
    const int q3 = tid & 127;
    const int kh = tid >> 7;
    const float4* w4 = (const float4*)s_w;

    // gather mapping
    const int gm  = tid & 15;
    const int gk4 = tid >> 4;

    // update mapping (u constant across reps since 256 % 64 == 0)
    const int uu = tid & 63;

    // static balanced schedule: 2*NSM-NCHUNK largest chunks run alone;
    // remaining blocks pair chunk b with chunk (small side), sums ~equal
    int my_chunks[2];
    int n_my = 0;
    {
        const int nsm = gridDim.x;
        const int b   = blockIdx.x;
        if (b < NCHUNK) my_chunks[n_my++] = b;
        const int singles = 2 * nsm - NCHUNK;
        if (singles >= 0) {
            if (b >= singles && b < nsm) my_chunks[n_my++] = NCHUNK - 1 - (b - singles);
        } else {
            const int c2 = b + nsm;          // fallback: grid-stride (not hit at 148/152 SMs)
            if (c2 < NCHUNK) my_chunks[n_my++] = c2;
        }
    }

    for (int ci = 0; ci < n_my; ci++) {
        const int chunk = my_chunks[ci];
        __syncthreads();
        if (tid < NB) {
            const int node = d_sorted[chunk * NB + tid];
            s_node[tid] = node;
            s_L[tid]    = sl[node];
        }
        for (int idx = tid; idx < 64 * XP; idx += 256) h_sm[idx] = 0.f;
        for (int idx = tid; idx < 16 * 64; idx += 256) c_sm[idx] = 0.f;
        __syncthreads();
        if (tid == 0) {
            int mx = 0;
            for (int m = 0; m < NB; m++) mx = max(mx, s_L[m]);
            s_meta[0] = mx;
        }
        __syncthreads();
        const int maxL = s_meta[0];
        const int Lg   = s_L[gm];
        const int obase = s_node[gm] * MAX_DEG;
        const float bu0 = s_b[uu], bu1 = s_b[64 + uu];
        const float bu2 = s_b[128 + uu], bu3 = s_b[192 + uu];

        // prefetch x for t=0
        float4 xv;
        {
            int idx = Lg - 1; if (idx < 0) idx = 0;
            const int row = d_ord[obase + idx];
            xv = *(const float4*)(&d_Wh2[row * F_OUT + gk4 * 4]);
        }

        for (int t = 0; t < maxL; t++) {
            // phase A: write x(t); state update for step t-1 (partials + bias)
            x_sm[(gk4 * 4 + 0) * XP + gm] = xv.x;
            x_sm[(gk4 * 4 + 1) * XP + gm] = xv.y;
            x_sm[(gk4 * 4 + 2) * XP + gm] = xv.z;
            x_sm[(gk4 * 4 + 3) * XP + gm] = xv.w;
            if (t + 1 < maxL) {
                int idx = Lg - 2 - t; if (idx < 0) idx = 0;
                const int row = d_ord[obase + idx];
                xv = *(const float4*)(&d_Wh2[row * F_OUT + gk4 * 4]);
            }
            if (t > 0) {
#pragma unroll
                for (int rep = 0; rep < 4; rep++) {
                    const int m = (tid >> 6) + rep * 4;
                    if (t - 1 < s_L[m]) {
                        const int gbase = m * GP + uu;
                        const float gi = g_a[gbase]       + g_b[gbase]       + bu0;
                        const float gf = g_a[gbase + 64]  + g_b[gbase + 64]  + bu1;
                        const float gg = g_a[gbase + 128] + g_b[gbase + 128] + bu2;
                        const float go = g_a[gbase + 192] + g_b[gbase + 192] + bu3;
                        const float c  = c_sm[m * 64 + uu];
                        const float cn = sigf(gf) * c + sigf(gi) * tanhfast(gg);
                        const float hn = sigf(go) * tanhfast(cn);
                        c_sm[m * 64 + uu] = cn;
                        h_sm[uu * XP + m] = hn;
                    }
                }
            }
            __syncthreads();

            // phase B: split-k gate GEMM, f32x2 over node pairs, 16 nodes/thread
            ull ag0[8], ag1[8];
#pragma unroll
            for (int j = 0; j < 8; j++) { ag0[j] = 0ull; ag1[j] = 0ull; }
#pragma unroll 4
            for (int k2 = 0; k2 < 32; k2++) {
                const int k = (kh << 5) + k2;
                const float4 w = w4[k * 128 + q3];
                const ull wi0 = pack2(w.x), wi1 = pack2(w.y);
                const ull wh0 = pack2(w.z), wh1 = pack2(w.w);
                const float* xr = x_sm + k * XP;
                const float* hr = h_sm + k * XP;
                const ulonglong2 x0 = *(const ulonglong2*)(xr);
                const ulonglong2 x1 = *(const ulonglong2*)(xr + 4);
                const ulonglong2 x2 = *(const ulonglong2*)(xr + 8);
                const ulonglong2 x3 = *(const ulonglong2*)(xr + 12);
                const ulonglong2 h0 = *(const ulonglong2*)(hr);
                const ulonglong2 h1 = *(const ulonglong2*)(hr + 4);
                const ulonglong2 h2 = *(const ulonglong2*)(hr + 8);
                const ulonglong2 h3 = *(const ulonglong2*)(hr + 12);
                fma2(ag0[0], wi0, x0.x); fma2(ag0[1], wi0, x0.y);
                fma2(ag0[2], wi0, x1.x); fma2(ag0[3], wi0, x1.y);
                fma2(ag0[4], wi0, x2.x); fma2(ag0[5], wi0, x2.y);
                fma2(ag0[6], wi0, x3.x); fma2(ag0[7], wi0, x3.y);
                fma2(ag1[0], wi1, x0.x); fma2(ag1[1], wi1, x0.y);
                fma2(ag1[2], wi1, x1.x); fma2(ag1[3], wi1, x1.y);
                fma2(ag1[4], wi1, x2.x); fma2(ag1[5], wi1, x2.y);
                fma2(ag1[6], wi1, x3.x); fma2(ag1[7], wi1, x3.y);
                fma2(ag0[0], wh0, h0.x); fma2(ag0[1], wh0, h0.y);
                fma2(ag0[2], wh0, h1.x); fma2(ag0[3], wh0, h1.y);
                fma2(ag0[4], wh0, h2.x); fma2(ag0[5], wh0, h2.y);
                fma2(ag0[6], wh0, h3.x); fma2(ag0[7], wh0, h3.y);
                fma2(ag1[0], wh1, h0.x); fma2(ag1[1], wh1, h0.y);
                fma2(ag1[2], wh1, h1.x); fma2(ag1[3], wh1, h1.y);
                fma2(ag1[4], wh1, h2.x); fma2(ag1[5], wh1, h2.y);
                fma2(ag1[6], wh1, h3.x); fma2(ag1[7], wh1, h3.y);
            }
            {
                float* gbase = (kh == 0) ? g_a : g_b;
#pragma unroll
                for (int j = 0; j < 8; j++) {
                    const float2 p0 = unpk(ag0[j]);     // gate 2q3, nodes 2j/2j+1
                    const float2 p1 = unpk(ag1[j]);     // gate 2q3+1
                    *(float2*)(gbase + (2 * j) * GP + 2 * q3)     = make_float2(p0.x, p1.x);
                    *(float2*)(gbase + (2 * j + 1) * GP + 2 * q3) = make_float2(p0.y, p1.y);
                }
            }
            __syncthreads();
        }

        // final update for step maxL-1
#pragma unroll
        for (int rep = 0; rep < 4; rep++) {
            const int m = (tid >> 6) + rep * 4;
            if (maxL - 1 < s_L[m]) {
                const int gbase = m * GP + uu;
                const float gi = g_a[gbase]       + g_b[gbase]       + bu0;
                const float gf = g_a[gbase + 64]  + g_b[gbase + 64]  + bu1;
                const float gg = g_a[gbase + 128] + g_b[gbase + 128] + bu2;
                const float go = g_a[gbase + 192] + g_b[gbase + 192] + bu3;
                const float c  = c_sm[m * 64 + uu];
                const float cn = sigf(gf) * c + sigf(gi) * tanhfast(gg);
                const float hn = sigf(go) * tanhfast(cn);
                c_sm[m * 64 + uu] = cn;
                h_sm[uu * XP + m] = hn;
            }
        }
        __syncthreads();

        // write hn
#pragma unroll
        for (int rep = 0; rep < 4; rep++) {
            const int m = (tid >> 6) + rep * 4;
            out[s_node[m] * HDIM + uu] = h_sm[uu * XP + m];
        }
    }
}

// ------------------------- launch ------------------------------------------
extern "C" void kernel_launch(void* const* d_in, const int* in_sizes, int n_in,
                              void* d_out, int out_size) {
    const float* h   = (const float*)d_in[0];
    const float* adj = (const float*)d_in[1];
    const int*   sl  = (const int*)  d_in[2];
    const float* W   = (const float*)d_in[3];
    const float* a   = (const float*)d_in[4];
    const float* wih = (const float*)d_in[5];
    const float* whh = (const float*)d_in[6];
    const float* bih = (const float*)d_in[7];
    const float* bhh = (const float*)d_in[8];
    float* out = (float*)d_out;

    cudaFuncSetAttribute(k_wh,   cudaFuncAttributeMaxDynamicSharedMemorySize, 96 * 1024);
    cudaFuncSetAttribute(k_lstm, cudaFuncAttributeMaxDynamicSharedMemorySize, LSTM_SMEM_BYTES);

    int sms = 148;
    cudaDeviceGetAttribute(&sms, cudaDevAttrMultiProcessorCount, 0);

    // k_lstm is my launch index 3: with 2 harness pre-launches, ncu -s 5 lands on it
    k_wh  <<<128,  256, 96 * 1024>>>(h, W, a);                           // 0
    k_att <<<4096, 256>>>(adj);                                          // 1
    k_sort<<<1,   1024>>>(sl);                                           // 2
    k_lstm<<<sms,  256, LSTM_SMEM_BYTES>>>(wih, whh, bih, bhh, sl, out); // 3
}

// round 16
// speedup vs baseline: 2.5688x; 1.7599x over previous
#include <cuda_runtime.h>
#include <cstdint>

#define N_NODES 4096
#define F_IN    256
#define F_OUT   64
#define HDIM    64
#define MAX_DEG 64
#define ALPHA   0.2f

#define NB      16                 // nodes per LSTM block
#define NCHUNK  (N_NODES / NB)     // 256 chunks
#define GP      260                // gates smem pitch (floats)

typedef unsigned long long ull;

// ------------------------- device scratch (no mallocs allowed) -------------
__device__ float d_Wh [N_NODES * F_OUT];
__device__ float d_Wh2[N_NODES * F_OUT];
__device__ float d_e1 [N_NODES];
__device__ float d_e2 [N_NODES];
__device__ int   d_ord[N_NODES * MAX_DEG];
__device__ int   d_sorted[N_NODES];

// ------------------------- K0: Wh = h @ W, fused e1/e2 ---------------------
__global__ void k_wh(const float* __restrict__ h, const float* __restrict__ W,
                     const float* __restrict__ a) {
    extern __shared__ float sm[];
    float* Wsm = sm;                       // [256][64]
    float* hsm = sm + F_IN * F_OUT;        // [32][256], reused as Wh stage
    __shared__ float a_sm[128];
    const int tid = threadIdx.x;
    const int r0  = blockIdx.x * 32;
    for (int i = tid; i < F_IN * F_OUT; i += 256) Wsm[i] = W[i];
    for (int i = tid; i < 32 * F_IN;    i += 256) hsm[i] = h[(size_t)r0 * F_IN + i];
    if (tid < 128) a_sm[tid] = a[tid];
    __syncthreads();
    const int f  = tid & 63;
    const int rq = tid >> 6;
    float acc[8];
#pragma unroll
    for (int j = 0; j < 8; j++) acc[j] = 0.f;
    for (int k = 0; k < F_IN; k++) {
        const float w = Wsm[k * F_OUT + f];
#pragma unroll
        for (int j = 0; j < 8; j++)
            acc[j] = fmaf(w, hsm[(rq * 8 + j) * F_IN + k], acc[j]);
    }
    __syncthreads();
    float* whs = hsm;                      // reuse: [32][64]
#pragma unroll
    for (int j = 0; j < 8; j++) {
        const int row = rq * 8 + j;
        whs[row * 64 + f] = acc[j];
        d_Wh[(r0 + row) * F_OUT + f] = acc[j];
    }
    __syncthreads();

    const int warp = tid >> 5, lane = tid & 31;
#pragma unroll
    for (int rr = 0; rr < 4; rr++) {
        const int row = warp * 4 + rr;
        const float v0 = whs[row * 64 + lane];
        const float v1 = whs[row * 64 + 32 + lane];
        float s1 = v0 * a_sm[lane]      + v1 * a_sm[lane + 32];
        float s2 = v0 * a_sm[64 + lane] + v1 * a_sm[96 + lane];
#pragma unroll
        for (int o = 16; o; o >>= 1) {
            s1 += __shfl_xor_sync(0xffffffffu, s1, o);
            s2 += __shfl_xor_sync(0xffffffffu, s2, o);
        }
        if (lane == 0) { d_e1[r0 + row] = s1; d_e2[r0 + row] = s2; }
    }
}

// ------------------------- K1: attention per node (low-barrier) ------------
__global__ void k_att(const float* __restrict__ adj) {
    __shared__ int   nbr[64];
    __shared__ float satt[64];
    __shared__ int   wsum[8];
    __shared__ float smax, ssum;
    __shared__ float spart[4][64];

    const int i    = blockIdx.x;
    const int tid  = threadIdx.x;
    const int warp = tid >> 5;
    const int lane = tid & 31;

    const float4* row = (const float4*)(adj + (size_t)i * N_NODES);
    float4 v[4];
#pragma unroll
    for (int j = 0; j < 4; j++) v[j] = row[tid * 4 + j];
    int cnt = 0;
#pragma unroll
    for (int j = 0; j < 4; j++)
        cnt += (v[j].x > 0.f) + (v[j].y > 0.f) + (v[j].z > 0.f) + (v[j].w > 0.f);

    int incl = cnt;
#pragma unroll
    for (int o = 1; o < 32; o <<= 1) {
        const int nv = __shfl_up_sync(0xffffffffu, incl, o);
        if (lane >= o) incl += nv;
    }
    if (lane == 31) wsum[warp] = incl;
    __syncthreads();
    int woff = 0, total = 0;
#pragma unroll
    for (int w = 0; w < 8; w++) {
        const int c = wsum[w];
        if (w < warp) woff += c;
        total += c;
    }
    int pos = woff + incl - cnt;

#pragma unroll
    for (int j = 0; j < 4; j++) {
        const int c0 = tid * 16 + j * 4;
        if (v[j].x > 0.f) { if (pos < 64) nbr[pos] = c0;     pos++; }
        if (v[j].y > 0.f) { if (pos < 64) nbr[pos] = c0 + 1; pos++; }
        if (v[j].z > 0.f) { if (pos < 64) nbr[pos] = c0 + 2; pos++; }
        if (v[j].w > 0.f) { if (pos < 64) nbr[pos] = c0 + 3; pos++; }
    }
    __syncthreads();
    const int L = (total < 64) ? total : 64;

    const float e1i = d_e1[i];
    if (tid < L) {
        float ev = e1i + d_e2[nbr[tid]];
        ev = ev > 0.f ? ev : ALPHA * ev;
        satt[tid] = ev;
    }
    __syncthreads();
    if (tid == 0) {
        float mx = satt[0];
        for (int n = 1; n < L; n++) mx = fmaxf(mx, satt[n]);
        smax = mx;
    }
    __syncthreads();
    if (tid < L) satt[tid] = __expf(satt[tid] - smax);
    __syncthreads();
    if (tid == 0) {
        float s = 0.f;
        for (int n = 0; n < L; n++) s += satt[n];
        ssum = s;
    }
    __syncthreads();
    if (tid < L) satt[tid] = satt[tid] / ssum;
    __syncthreads();

    if (tid < L) {
        const float av = satt[tid];
        const int   jv = nbr[tid];
        int rank = 0;
        for (int k = 0; k < L; k++) {
            const float ak = satt[k];
            rank += (ak > av) || (ak == av && nbr[k] < jv);
        }
        d_ord[i * MAX_DEG + rank] = jv;
    }

    const int f = tid & 63, s = tid >> 6;
    float part = 0.f;
    for (int n = s; n < L; n += 4)
        part = fmaf(satt[n], d_Wh[nbr[n] * F_OUT + f], part);
    spart[s][f] = part;
    __syncthreads();
    if (s == 0)
        d_Wh2[i * F_OUT + f] = spart[0][f] + spart[1][f] + spart[2][f] + spart[3][f];
}

// ------------------------- K2: counting sort (single block) ----------------
__global__ void k_sort(const int* __restrict__ sl) {
    __shared__ int hist[64];
    __shared__ int off[64];
    const int t = threadIdx.x;
    if (t < 64) hist[t] = 0;
    __syncthreads();
    for (int i = t; i < N_NODES; i += 1024) atomicAdd(&hist[64 - sl[i]], 1);
    __syncthreads();
    if (t == 0) {
        int acc = 0;
        for (int b = 0; b < 64; b++) { off[b] = acc; acc += hist[b]; }
    }
    __syncthreads();
    for (int i = t; i < N_NODES; i += 1024) {
        const int p = atomicAdd(&off[64 - sl[i]], 1);
        d_sorted[p] = i;
    }
}

// ------------------------- K3: persistent LSTM (mma.sync tf32) -------------
// SMEM: w_frag 32768 u32 + b 256 + b_frag 2048 u32 + h_pl 1024 + c 1024 + g 4160
#define WF_U32   32768
#define BF_U32   2048
#define LSTM_SMEM_FLOATS (WF_U32 + 256 + BF_U32 + 1024 + 1024 + NB * GP)
#define LSTM_SMEM_BYTES  (LSTM_SMEM_FLOATS * 4 + 64 * 4)

#define LOG2E  1.4426950408889634f
#define LOG2E2 2.8853900817779268f
__device__ __forceinline__ float ex2a(float x) {
    float r; asm("ex2.approx.f32 %0, %1;" : "=f"(r) : "f"(x)); return r;
}
__device__ __forceinline__ float rcpa(float x) {
    float r; asm("rcp.approx.f32 %0, %1;" : "=f"(r) : "f"(x)); return r;
}
__device__ __forceinline__ float sigf(float x) {
    return rcpa(1.f + ex2a(-x * LOG2E));
}
__device__ __forceinline__ float tanhfast(float x) {
    return fmaf(-2.f, rcpa(ex2a(x * LOG2E2) + 1.f), 1.f);
}
__device__ __forceinline__ uint32_t f2tf32(float x) {
    uint32_t r; asm("cvt.rna.tf32.f32 %0, %1;" : "=r"(r) : "f"(x)); return r;
}
__device__ __forceinline__ void mma_tf32(float* d, const uint4& a, const uint2& b) {
    asm volatile(
        "mma.sync.aligned.m16n8k8.row.col.f32.tf32.tf32.f32 "
        "{%0,%1,%2,%3}, {%4,%5,%6,%7}, {%8,%9}, {%0,%1,%2,%3};"
        : "+f"(d[0]), "+f"(d[1]), "+f"(d[2]), "+f"(d[3])
        : "r"(a.x), "r"(a.y), "r"(a.z), "r"(a.w), "r"(b.x), "r"(b.y));
}
// B-fragment slot for XH[k][node]  (m16n8k8 col-major B, b0/b1 adjacent)
__device__ __forceinline__ int boff(int k, int node) {
    return (k >> 3) * 128 + (node >> 3) * 64 + (node & 7) * 8
         + (k & 3) * 2 + ((k >> 2) & 1);
}

__global__ __launch_bounds__(256, 1)
void k_lstm(const float* __restrict__ w_ih, const float* __restrict__ w_hh,
            const float* __restrict__ b_ih, const float* __restrict__ b_hh,
            const int* __restrict__ sl, float* __restrict__ out) {
    extern __shared__ float sm[];
    uint32_t* s_wf = (uint32_t*)sm;          // [16 Mt][16 kt][32 lane][4] tf32
    float* s_b   = sm + WF_U32;              // [256]
    uint32_t* s_bf = (uint32_t*)(s_b + 256); // [2048] B fragments (tf32)
    float* h_pl  = s_b + 256 + BF_U32;       // [16][64]
    float* c_sm  = h_pl + 1024;              // [16][64]
    float* g_sm  = c_sm + 1024;              // [16][GP] gates (bias included)
    int*   s_node = (int*)(g_sm + NB * GP);  // [16]
    int*   s_L    = s_node + NB;             // [16]
    int*   s_meta = s_L + NB;                // [0]=maxL

    const int tid  = threadIdx.x;
    const int lane = tid & 31;
    const int w    = tid >> 5;
    const int fg   = lane >> 2;   // fragment groupID
    const int ft   = lane & 3;    // fragment threadID-in-group

    // weight preload into A-fragment order (tf32), one-time
    for (int idx = tid; idx < WF_U32; idx += 256) {
        const int r  = idx & 3;
        const int ln = (idx >> 2) & 31;
        const int kt = (idx >> 7) & 15;
        const int Mt = idx >> 11;
        const int row = Mt * 16 + (ln >> 2) + (r & 1) * 8;
        const int col = kt * 8 + (ln & 3) + ((r >> 1) << 2);
        const float v = (col < 64) ? w_ih[row * 64 + col]
                                   : w_hh[row * 64 + col - 64];
        s_wf[idx] = f2tf32(v);
    }
    s_b[tid] = b_ih[tid] + b_hh[tid];
    __syncthreads();

    // per-warp bias fragments (row-constant across C columns)
    float bias_r[2][2];
#pragma unroll
    for (int mi = 0; mi < 2; mi++) {
        bias_r[mi][0] = s_b[(2 * w + mi) * 16 + fg];
        bias_r[mi][1] = s_b[(2 * w + mi) * 16 + 8 + fg];
    }

    // gather mapping
    const int gm  = tid & 15;
    const int gk4 = tid >> 4;
    // update mapping
    const int uu  = tid & 63;

    // static balanced schedule (R13)
    int my_chunks[2];
    int n_my = 0;
    {
        const int nsm = gridDim.x;
        const int b   = blockIdx.x;
        if (b < NCHUNK) my_chunks[n_my++] = b;
        const int singles = 2 * nsm - NCHUNK;
        if (singles >= 0) {
            if (b >= singles && b < nsm) my_chunks[n_my++] = NCHUNK - 1 - (b - singles);
        } else {
            const int c2 = b + nsm;
            if (c2 < NCHUNK) my_chunks[n_my++] = c2;
        }
    }

    for (int ci = 0; ci < n_my; ci++) {
        const int chunk = my_chunks[ci];
        __syncthreads();
        if (tid < NB) {
            const int node = d_sorted[chunk * NB + tid];
            s_node[tid] = node;
            s_L[tid]    = sl[node];
        }
        // zero h-part of B fragments (k 64..127 -> slots 1024..2047), h_pl, c
        for (int idx = tid; idx < 1024; idx += 256) {
            s_bf[1024 + idx] = 0u;
            h_pl[idx] = 0.f;
            c_sm[idx] = 0.f;
        }
        __syncthreads();
        if (tid == 0) {
            int mx = 0;
            for (int m = 0; m < NB; m++) mx = max(mx, s_L[m]);
            s_meta[0] = mx;
        }
        __syncthreads();
        const int maxL = s_meta[0];
        const int Lg   = s_L[gm];
        const int obase = s_node[gm] * MAX_DEG;

        // prefetch x for t=0
        float4 xv;
        {
            int idx = Lg - 1; if (idx < 0) idx = 0;
            const int row = d_ord[obase + idx];
            xv = *(const float4*)(&d_Wh2[row * F_OUT + gk4 * 4]);
        }

        for (int t = 0; t < maxL; t++) {
            // ---- phase A: write x(t) fragments; state update for step t-1
            {
                const int k0 = gk4 * 4;
                s_bf[boff(k0 + 0, gm)] = f2tf32(xv.x);
                s_bf[boff(k0 + 1, gm)] = f2tf32(xv.y);
                s_bf[boff(k0 + 2, gm)] = f2tf32(xv.z);
                s_bf[boff(k0 + 3, gm)] = f2tf32(xv.w);
            }
            if (t + 1 < maxL) {
                int idx = Lg - 2 - t; if (idx < 0) idx = 0;
                const int row = d_ord[obase + idx];
                xv = *(const float4*)(&d_Wh2[row * F_OUT + gk4 * 4]);
            }
            if (t > 0) {
#pragma unroll
                for (int rep = 0; rep < 4; rep++) {
                    const int m = (tid >> 6) + rep * 4;
                    if (t - 1 < s_L[m]) {
                        const int gb = m * GP + uu;
                        const float gi = g_sm[gb];
                        const float gf = g_sm[gb + 64];
                        const float gg = g_sm[gb + 128];
                        const float go = g_sm[gb + 192];
                        const float c  = c_sm[m * 64 + uu];
                        const float cn = sigf(gf) * c + sigf(gi) * tanhfast(gg);
                        const float hn = sigf(go) * tanhfast(cn);
                        c_sm[m * 64 + uu] = cn;
                        h_pl[m * 64 + uu] = hn;
                        s_bf[boff(64 + uu, m)] = f2tf32(hn);
                    }
                }
            }
            __syncthreads();

            // ---- phase B: tensor-core gate GEMM (64 MMAs per warp)
            float d00[4], d01[4], d10[4], d11[4];
#pragma unroll
            for (int j = 0; j < 2; j++) {
                d00[j * 2] = bias_r[0][j]; d00[j * 2 + 1] = bias_r[0][j];
                d01[j * 2] = bias_r[0][j]; d01[j * 2 + 1] = bias_r[0][j];
                d10[j * 2] = bias_r[1][j]; d10[j * 2 + 1] = bias_r[1][j];
                d11[j * 2] = bias_r[1][j]; d11[j * 2 + 1] = bias_r[1][j];
            }
            // note: accumulator layout c0/c1 = row fg (bias_r[.][0]); c2/c3 = row fg+8
#pragma unroll
            for (int kt = 0; kt < 16; kt++) {
                const uint4 A0 = *(const uint4*)&s_wf[(((2 * w + 0) * 16 + kt) * 32 + lane) * 4];
                const uint4 A1 = *(const uint4*)&s_wf[(((2 * w + 1) * 16 + kt) * 32 + lane) * 4];
                const uint2 B0 = *(const uint2*)&s_bf[((kt * 2 + 0) * 32 + lane) * 2];
                const uint2 B1 = *(const uint2*)&s_bf[((kt * 2 + 1) * 32 + lane) * 2];
                mma_tf32(d00, A0, B0);
                mma_tf32(d01, A0, B1);
                mma_tf32(d10, A1, B0);
                mma_tf32(d11, A1, B1);
            }
            // store C: g_sm[node][gate]
            {
                const int Mb0 = (2 * w) * 16, Mb1 = (2 * w + 1) * 16;
                const int r0 = (2 * ft) * GP, r1 = (2 * ft + 1) * GP;
                g_sm[r0 + Mb0 + fg]          = d00[0];
                g_sm[r1 + Mb0 + fg]          = d00[1];
                g_sm[r0 + Mb0 + 8 + fg]      = d00[2];
                g_sm[r1 + Mb0 + 8 + fg]      = d00[3];
                g_sm[r0 + 8 * GP + Mb0 + fg]     = d01[0];
                g_sm[r1 + 8 * GP + Mb0 + fg]     = d01[1];
                g_sm[r0 + 8 * GP + Mb0 + 8 + fg] = d01[2];
                g_sm[r1 + 8 * GP + Mb0 + 8 + fg] = d01[3];
                g_sm[r0 + Mb1 + fg]          = d10[0];
                g_sm[r1 + Mb1 + fg]          = d10[1];
                g_sm[r0 + Mb1 + 8 + fg]      = d10[2];
                g_sm[r1 + Mb1 + 8 + fg]      = d10[3];
                g_sm[r0 + 8 * GP + Mb1 + fg]     = d11[0];
                g_sm[r1 + 8 * GP + Mb1 + fg]     = d11[1];
                g_sm[r0 + 8 * GP + Mb1 + 8 + fg] = d11[2];
                g_sm[r1 + 8 * GP + Mb1 + 8 + fg] = d11[3];
            }
            __syncthreads();
        }

        // final update for step maxL-1
#pragma unroll
        for (int rep = 0; rep < 4; rep++) {
            const int m = (tid >> 6) + rep * 4;
            if (maxL - 1 < s_L[m]) {
                const int gb = m * GP + uu;
                const float gi = g_sm[gb];
                const float gf = g_sm[gb + 64];
                const float gg = g_sm[gb + 128];
                const float go = g_sm[gb + 192];
                const float c  = c_sm[m * 64 + uu];
                const float cn = sigf(gf) * c + sigf(gi) * tanhfast(gg);
                const float hn = sigf(go) * tanhfast(cn);
                h_pl[m * 64 + uu] = hn;
            }
        }
        __syncthreads();

        // write hn
#pragma unroll
        for (int rep = 0; rep < 4; rep++) {
            const int m = (tid >> 6) + rep * 4;
            out[s_node[m] * HDIM + uu] = h_pl[m * 64 + uu];
        }
    }
}

// ------------------------- launch ------------------------------------------
extern "C" void kernel_launch(void* const* d_in, const int* in_sizes, int n_in,
                              void* d_out, int out_size) {
    const float* h   = (const float*)d_in[0];
    const float* adj = (const float*)d_in[1];
    const int*   sl  = (const int*)  d_in[2];
    const float* W   = (const float*)d_in[3];
    const float* a   = (const float*)d_in[4];
    const float* wih = (const float*)d_in[5];
    const float* whh = (const float*)d_in[6];
    const float* bih = (const float*)d_in[7];
    const float* bhh = (const float*)d_in[8];
    float* out = (float*)d_out;

    cudaFuncSetAttribute(k_wh,   cudaFuncAttributeMaxDynamicSharedMemorySize, 96 * 1024);
    cudaFuncSetAttribute(k_lstm, cudaFuncAttributeMaxDynamicSharedMemorySize, LSTM_SMEM_BYTES);

    int sms = 148;
    cudaDeviceGetAttribute(&sms, cudaDevAttrMultiProcessorCount, 0);

    // k_lstm is my launch index 3: with 2 harness pre-launches, ncu -s 5 lands on it
    k_wh  <<<128,  256, 96 * 1024>>>(h, W, a);                           // 0
    k_att <<<4096, 256>>>(adj);                                          // 1
    k_sort<<<1,   1024>>>(sl);                                           // 2
    k_lstm<<<sms,  256, LSTM_SMEM_BYTES>>>(wih, whh, bih, bhh, sl, out); // 3
}